// round 14
// baseline (speedup 1.0000x reference)
#include <cuda_runtime.h>
#include <math.h>
#include <stdint.h>

#define DIM      768
#define HEADS    12
#define HD       64
#define HIDDEN   3072
#define SEQ      577
#define BATCH    64
#define NTOK     (BATCH*SEQ)  // 36928
#define QKVD     (3*DIM)      // 2304

// ---------------- scratch arena (word = uint32) ----------------
#define QKV_W   ((size_t)NTOK * QKVD)          // fp32
#define X2_W    ((size_t)NTOK * DIM)           // fp32
#define HP_W    ((size_t)NTOK * DIM / 2)       // one bf16 plane of h/O
#define MP_W    ((size_t)NTOK * HIDDEN / 2)    // one bf16 plane of m
#define WQKV_W  ((size_t)DIM * QKVD / 2)       // one plane
#define WPROJ_W ((size_t)DIM * DIM / 2)
#define W1_W    ((size_t)DIM * HIDDEN / 2)
#define W2_W    ((size_t)HIDDEN * DIM / 2)
#define ARENA_WORDS (QKV_W + X2_W + 2*HP_W + 2*MP_W + 2*WQKV_W + 2*WPROJ_W + 2*W1_W + 2*W2_W)
__device__ __align__(16) uint32_t g_arena[ARENA_WORDS];

// ---------------- helpers ----------------
__device__ __forceinline__ uint32_t smem_u32(const void* p) {
    uint32_t a;
    asm("{ .reg .u64 t; cvta.to.shared.u64 t, %1; cvt.u32.u64 %0, t; }"
        : "=r"(a) : "l"(p));
    return a;
}
// word = bf16(hi)<<16 | bf16(lo), RNE
__device__ __forceinline__ uint32_t cvt_bf16x2(float hi, float lo) {
    uint32_t r;
    asm("cvt.rn.bf16x2.f32 %0, %1, %2;" : "=r"(r) : "f"(hi), "f"(lo));
    return r;
}
__device__ __forceinline__ uint32_t bf16h(float f) {
    uint32_t u = __float_as_uint(f);
    return (u + 0x7FFFu + ((u >> 16) & 1u)) >> 16;
}
__device__ __forceinline__ float bf16f(uint32_t h) {
    return __uint_as_float(h << 16);
}

#define LDSM4(r0, r1, r2, r3, addr) \
    asm volatile("ldmatrix.sync.aligned.m8n8.x4.shared.b16 {%0,%1,%2,%3}, [%4];" \
                 : "=r"(r0), "=r"(r1), "=r"(r2), "=r"(r3) : "r"(addr))

#define MMA_BF16(d, a, b) \
    asm volatile("mma.sync.aligned.m16n8k16.row.col.f32.bf16.bf16.f32 " \
                 "{%0,%1,%2,%3}, {%4,%5,%6,%7}, {%8,%9}, {%0,%1,%2,%3};" \
                 : "+f"((d)[0]), "+f"((d)[1]), "+f"((d)[2]), "+f"((d)[3]) \
                 : "r"((a)[0]), "r"((a)[1]), "r"((a)[2]), "r"((a)[3]), \
                   "r"((b)[0]), "r"((b)[1]))

#define CPA(dst, src, sz) \
    asm volatile("cp.async.cg.shared.global [%0], [%1], 16, %2;" \
                 :: "r"(dst), "l"(src), "r"(sz))
#define CP_COMMIT() asm volatile("cp.async.commit_group;")
#define CP_WAIT1()  asm volatile("cp.async.wait_group 1;")

// ============ plane-based bf16-split GEMM: 128x256 tile, k-block 32 =========
// A planes Ah/Al [M][K] bf16, B planes Bh/Bl [N][K] bf16 (K-major rows).
// D += Ah*Bh + Ah*Bl + Al*Bh  (3-term split, fp32 accum).
// 8 warps (2x4), 64x64 warp tile. 3-stage cp.async pipeline.
#define APITCH  80                       // 32 bf16 (64B) + 16B pad
#define APL     (128 * APITCH)           // 10240 per A plane
#define BPL     (256 * APITCH)           // 20480 per B plane
#define STAGEB  (2 * APL + 2 * BPL)      // 61440
#define GEMM_SMEM (3 * STAGEB)           // 184320

template<bool BIAS, bool GELU, bool RES, bool OUTX>
__global__ __launch_bounds__(256, 1) void tcgemm_kernel(
    const uint16_t* __restrict__ Ahg, const uint16_t* __restrict__ Alg,
    const uint16_t* __restrict__ Bhg, const uint16_t* __restrict__ Blg,
    const float* __restrict__ bias, const float* __restrict__ res,
    float* __restrict__ C, uint32_t* __restrict__ Ch, uint32_t* __restrict__ Cl,
    int M, int N, int K)
{
    extern __shared__ char smem[];
    const uint32_t sb = smem_u32(smem);
    const int tid  = threadIdx.x;
    const int lane = tid & 31;
    const int wid  = tid >> 5;
    const int wr = wid >> 2, wc = wid & 3;
    const int m0w = wr * 64, n0w = wc * 64;

    const int m0 = blockIdx.y * 128, col0 = blockIdx.x * 256;
    const int NBLK = K >> 5;
    const size_t KB = (size_t)K * 2;     // bytes per plane row

    // ---- loader setup ----
    const int arow = tid >> 1;                    // 0..127
    const int aoff = (tid & 1) * 32;              // 0 or 32 bytes
    const int gar = m0 + arow;
    const uint32_t asz = (gar < M) ? 16u : 0u;
    const char* srcAh = (const char*)Ahg + (size_t)(gar < M ? gar : 0) * KB + aoff;
    const char* srcAl = (const char*)Alg + (size_t)(gar < M ? gar : 0) * KB + aoff;
    const char* srcBh = (const char*)Bhg + (size_t)(col0 + tid) * KB;
    const char* srcBl = (const char*)Blg + (size_t)(col0 + tid) * KB;
    const uint32_t dAh = arow * APITCH + aoff;
    const uint32_t dB  = 2 * APL + tid * APITCH;

    float dacc[32][4];
    #pragma unroll
    for (int t = 0; t < 32; t++)
        #pragma unroll
        for (int c = 0; c < 4; c++) dacc[t][c] = 0.f;

    auto issue_block = [&](int blk, int stage) {
        const uint32_t ss = sb + stage * STAGEB;
        const size_t go = (size_t)blk * 64;
        CPA(ss + dAh,            srcAh + go,      asz);
        CPA(ss + dAh + 16,       srcAh + go + 16, asz);
        CPA(ss + APL + dAh,      srcAl + go,      asz);
        CPA(ss + APL + dAh + 16, srcAl + go + 16, asz);
        #pragma unroll
        for (int i = 0; i < 4; i++) {
            CPA(ss + dB + i * 16,       srcBh + go + i * 16, 16u);
            CPA(ss + dB + BPL + i * 16, srcBl + go + i * 16, 16u);
        }
    };

    // ---- prologue ----
    issue_block(0, 0); CP_COMMIT();
    if (NBLK > 1) issue_block(1, 1);
    CP_COMMIT();

    for (int blk = 0; blk < NBLK; blk++) {
        CP_WAIT1();
        __syncthreads();
        if (blk + 2 < NBLK) {
            int ns = blk + 2; ns -= (ns >= 3) ? ((ns / 3) * 3) : 0;  // (blk+2)%3
            issue_block(blk + 2, ns);
        }
        CP_COMMIT();

        const int stage = blk % 3;
        const uint32_t ss = sb + stage * STAGEB;
        const uint32_t aH = ss + (uint32_t)(m0w + (lane & 15)) * APITCH
                               + ((lane >> 4) * 16);
        const int g = lane >> 3;
        const uint32_t bH = ss + 2 * APL
                               + (uint32_t)(n0w + (g >> 1) * 8 + (lane & 7)) * APITCH
                               + (g & 1) * 16;
        #pragma unroll
        for (int kc = 0; kc < 2; kc++) {
            uint32_t ah[4][4], al[4][4], bh[8][2], bl[8][2];
            #pragma unroll
            for (int mi = 0; mi < 4; mi++) {
                LDSM4(ah[mi][0], ah[mi][1], ah[mi][2], ah[mi][3],
                      aH + mi * 16 * APITCH + kc * 32);
                LDSM4(al[mi][0], al[mi][1], al[mi][2], al[mi][3],
                      aH + APL + mi * 16 * APITCH + kc * 32);
            }
            #pragma unroll
            for (int p = 0; p < 4; p++) {
                LDSM4(bh[2*p][0], bh[2*p][1], bh[2*p+1][0], bh[2*p+1][1],
                      bH + p * 16 * APITCH + kc * 32);
                LDSM4(bl[2*p][0], bl[2*p][1], bl[2*p+1][0], bl[2*p+1][1],
                      bH + BPL + p * 16 * APITCH + kc * 32);
            }
            #pragma unroll
            for (int mi = 0; mi < 4; mi++)
                #pragma unroll
                for (int nt = 0; nt < 8; nt++) {
                    MMA_BF16(dacc[mi * 8 + nt], ah[mi], bh[nt]);
                    MMA_BF16(dacc[mi * 8 + nt], ah[mi], bl[nt]);
                    MMA_BF16(dacc[mi * 8 + nt], al[mi], bh[nt]);
                }
        }
    }

    // ---- epilogue ----
    #pragma unroll
    for (int mi = 0; mi < 4; mi++) {
        const int r0 = m0 + m0w + mi * 16 + (lane >> 2);
        #pragma unroll
        for (int nt = 0; nt < 8; nt++) {
            const int c = col0 + n0w + nt * 8 + (lane & 3) * 2;
            const float* d = dacc[mi * 8 + nt];
            float b0 = 0.f, b1 = 0.f;
            if (BIAS) { b0 = bias[c]; b1 = bias[c + 1]; }
            #pragma unroll
            for (int half = 0; half < 2; half++) {
                const int r = r0 + half * 8;
                if (r >= M) continue;
                float v0 = d[half * 2 + 0] + b0;
                float v1 = d[half * 2 + 1] + b1;
                if (GELU) {
                    v0 = 0.5f * v0 * (1.0f + erff(v0 * 0.70710678118654752f));
                    v1 = 0.5f * v1 * (1.0f + erff(v1 * 0.70710678118654752f));
                }
                if (RES) {
                    const float2 rv = *reinterpret_cast<const float2*>(
                        res + (size_t)r * N + c);
                    v0 += rv.x; v1 += rv.y;
                }
                if (OUTX) {
                    const uint32_t hw = cvt_bf16x2(v1, v0);
                    const float f0h = __uint_as_float(hw << 16);
                    const float f1h = __uint_as_float(hw & 0xFFFF0000u);
                    const uint32_t lw = cvt_bf16x2(v1 - f1h, v0 - f0h);
                    const size_t w = ((size_t)r * N + c) >> 1;
                    Ch[w] = hw; Cl[w] = lw;
                } else {
                    *reinterpret_cast<float2*>(C + (size_t)r * N + c) =
                        make_float2(v0, v1);
                }
            }
        }
    }
}

// ---------------- weight split: W [K][N] fp32 -> Wh/Wl [N][K] bf16 ----------
__global__ __launch_bounds__(256) void splitw_kernel(
    const float* __restrict__ W, uint16_t* __restrict__ Wh,
    uint16_t* __restrict__ Wl, int K, int N)
{
    const size_t idx = (size_t)blockIdx.x * 256 + threadIdx.x;
    if (idx >= (size_t)N * K) return;
    const int n = (int)(idx / K), k = (int)(idx % K);
    const float v = W[(size_t)k * N + n];
    const uint32_t h = bf16h(v);
    Wh[idx] = (uint16_t)h;
    Wl[idx] = (uint16_t)bf16h(v - bf16f(h));
}

// ---------------- LayerNorm -> hi/lo bf16 planes (192 thr, float4) ----------
__global__ __launch_bounds__(192) void lnx2_kernel(
    const float* __restrict__ x, const float* __restrict__ g,
    const float* __restrict__ b, uint32_t* __restrict__ outh,
    uint32_t* __restrict__ outl)
{
    const size_t t = blockIdx.x;
    const int tid = threadIdx.x;
    const float4 v = *reinterpret_cast<const float4*>(x + t * DIM + tid * 4);

    float s  = v.x + v.y + v.z + v.w;
    float ss = v.x*v.x + v.y*v.y + v.z*v.z + v.w*v.w;

    __shared__ float red[12];
    __shared__ float stat[2];
    #pragma unroll
    for (int o = 16; o; o >>= 1) {
        s  += __shfl_xor_sync(0xffffffffu, s,  o);
        ss += __shfl_xor_sync(0xffffffffu, ss, o);
    }
    if ((tid & 31) == 0) { red[tid >> 5] = s; red[(tid >> 5) + 6] = ss; }
    __syncthreads();
    if (tid == 0) {
        float a = 0.f, c = 0.f;
        #pragma unroll
        for (int i = 0; i < 6; i++) { a += red[i]; c += red[i + 6]; }
        const float mu = a * (1.0f / DIM);
        stat[0] = mu;
        stat[1] = rsqrtf(c * (1.0f / DIM) - mu * mu + 1e-5f);
    }
    __syncthreads();
    const float mu = stat[0], inv = stat[1];

    const float4 g4 = *reinterpret_cast<const float4*>(g + tid * 4);
    const float4 b4 = *reinterpret_cast<const float4*>(b + tid * 4);
    const float n0 = (v.x - mu) * inv * g4.x + b4.x;
    const float n1 = (v.y - mu) * inv * g4.y + b4.y;
    const float n2 = (v.z - mu) * inv * g4.z + b4.z;
    const float n3 = (v.w - mu) * inv * g4.w + b4.w;

    const uint32_t h0 = cvt_bf16x2(n1, n0);
    const uint32_t h1 = cvt_bf16x2(n3, n2);
    const uint32_t l0 = cvt_bf16x2(n1 - __uint_as_float(h0 & 0xFFFF0000u),
                                   n0 - __uint_as_float(h0 << 16));
    const uint32_t l1 = cvt_bf16x2(n3 - __uint_as_float(h1 & 0xFFFF0000u),
                                   n2 - __uint_as_float(h1 << 16));
    const size_t w2 = t * 192 + tid;          // uint2 index
    reinterpret_cast<uint2*>(outh)[w2] = make_uint2(h0, h1);
    reinterpret_cast<uint2*>(outl)[w2] = make_uint2(l0, l1);
}

// ---------------- Fused flash attention -> hi/lo planes ----------------
#define FA_SMEM (3 * 64 * 68 * 4)

__global__ __launch_bounds__(256) void fattn_kernel(
    const float* __restrict__ qkv, uint32_t* __restrict__ Oh,
    uint32_t* __restrict__ Ol)
{
    extern __shared__ float sm[];
    float (*Qs)[68] = reinterpret_cast<float(*)[68]>(sm);
    float (*KP)[68] = reinterpret_cast<float(*)[68]>(sm + 64 * 68);
    float (*Vs)[68] = reinterpret_cast<float(*)[68]>(sm + 2 * 64 * 68);

    const int bh = blockIdx.y;
    const int b = bh / HEADS, h = bh % HEADS;
    const int n0 = blockIdx.x * 64;
    const float* qb = qkv + (size_t)b * SEQ * QKVD + h * HD;
    const float* kb = qb + DIM;
    const float* vb = qb + 2 * DIM;

    const int tid = threadIdx.x;
    const int lr = tid >> 2;
    const int lc = (tid & 3) * 16;
    const int tx = tid & 15, ty = tid >> 4;

    {
        const int n = n0 + lr;
        const float4* src = (n < SEQ)
            ? reinterpret_cast<const float4*>(qb + (size_t)n * QKVD + lc) : nullptr;
        #pragma unroll
        for (int c4 = 0; c4 < 4; c4++) {
            float4 v = src ? src[c4] : make_float4(0.f,0.f,0.f,0.f);
            const int d = lc + c4 * 4;
            Qs[d][lr]=v.x; Qs[d+1][lr]=v.y; Qs[d+2][lr]=v.z; Qs[d+3][lr]=v.w;
        }
    }

    float acc_o[4][4];
    float row_m[4], row_l[4];
    #pragma unroll
    for (int i = 0; i < 4; i++) {
        row_m[i] = -1e30f; row_l[i] = 0.f;
        #pragma unroll
        for (int j = 0; j < 4; j++) acc_o[i][j] = 0.f;
    }

    for (int k0 = 0; k0 < SEQ; k0 += 64) {
        __syncthreads();
        {
            const int m = k0 + lr;
            const float4* srck = (m < SEQ)
                ? reinterpret_cast<const float4*>(kb + (size_t)m * QKVD + lc) : nullptr;
            const float4* srcv = (m < SEQ)
                ? reinterpret_cast<const float4*>(vb + (size_t)m * QKVD + lc) : nullptr;
            #pragma unroll
            for (int c4 = 0; c4 < 4; c4++) {
                float4 v = srck ? srck[c4] : make_float4(0.f,0.f,0.f,0.f);
                const int d = lc + c4 * 4;
                KP[d][lr]=v.x; KP[d+1][lr]=v.y; KP[d+2][lr]=v.z; KP[d+3][lr]=v.w;
                float4 w = srcv ? srcv[c4] : make_float4(0.f,0.f,0.f,0.f);
                *reinterpret_cast<float4*>(&Vs[lr][lc + c4 * 4]) = w;
            }
        }
        __syncthreads();

        float s[4][4];
        #pragma unroll
        for (int i = 0; i < 4; i++)
            #pragma unroll
            for (int j = 0; j < 4; j++) s[i][j] = 0.f;

        #pragma unroll 8
        for (int d = 0; d < 64; d++) {
            float4 ra = *reinterpret_cast<const float4*>(&Qs[d][ty * 4]);
            float4 rb = *reinterpret_cast<const float4*>(&KP[d][tx * 4]);
            float a[4] = {ra.x, ra.y, ra.z, ra.w};
            float bb[4] = {rb.x, rb.y, rb.z, rb.w};
            #pragma unroll
            for (int i = 0; i < 4; i++)
                #pragma unroll
                for (int j = 0; j < 4; j++)
                    s[i][j] = fmaf(a[i], bb[j], s[i][j]);
        }

        #pragma unroll
        for (int i = 0; i < 4; i++)
            #pragma unroll
            for (int j = 0; j < 4; j++) {
                s[i][j] *= 0.125f;
                if (k0 + tx * 4 + j >= SEQ) s[i][j] = -1e30f;
            }

        float f[4];
        #pragma unroll
        for (int i = 0; i < 4; i++) {
            float mt = fmaxf(fmaxf(s[i][0], s[i][1]), fmaxf(s[i][2], s[i][3]));
            #pragma unroll
            for (int o = 1; o < 16; o <<= 1)
                mt = fmaxf(mt, __shfl_xor_sync(0xffffffffu, mt, o, 16));
            const float nm = fmaxf(row_m[i], mt);
            f[i] = __expf(row_m[i] - nm);
            row_m[i] = nm;
            float rs = 0.f;
            #pragma unroll
            for (int j = 0; j < 4; j++) {
                s[i][j] = __expf(s[i][j] - nm);
                rs += s[i][j];
            }
            #pragma unroll
            for (int o = 1; o < 16; o <<= 1)
                rs += __shfl_xor_sync(0xffffffffu, rs, o, 16);
            row_l[i] = row_l[i] * f[i] + rs;
            #pragma unroll
            for (int j = 0; j < 4; j++) acc_o[i][j] *= f[i];
        }

        __syncthreads();
        #pragma unroll
        for (int i = 0; i < 4; i++)
            *reinterpret_cast<float4*>(&KP[ty * 4 + i][tx * 4]) =
                make_float4(s[i][0], s[i][1], s[i][2], s[i][3]);
        __syncthreads();

        #pragma unroll 4
        for (int k = 0; k < 64; k += 4) {
            float4 pa[4], vv[4];
            #pragma unroll
            for (int i = 0; i < 4; i++)
                pa[i] = *reinterpret_cast<const float4*>(&KP[ty * 4 + i][k]);
            #pragma unroll
            for (int kk = 0; kk < 4; kk++)
                vv[kk] = *reinterpret_cast<const float4*>(&Vs[k + kk][tx * 4]);
            #pragma unroll
            for (int i = 0; i < 4; i++) {
                float p[4] = {pa[i].x, pa[i].y, pa[i].z, pa[i].w};
                #pragma unroll
                for (int kk = 0; kk < 4; kk++) {
                    acc_o[i][0] = fmaf(p[kk], vv[kk].x, acc_o[i][0]);
                    acc_o[i][1] = fmaf(p[kk], vv[kk].y, acc_o[i][1]);
                    acc_o[i][2] = fmaf(p[kk], vv[kk].z, acc_o[i][2]);
                    acc_o[i][3] = fmaf(p[kk], vv[kk].w, acc_o[i][3]);
                }
            }
        }
    }

    #pragma unroll
    for (int i = 0; i < 4; i++) {
        const int n = n0 + ty * 4 + i;
        if (n >= SEQ) continue;
        const float inv = 1.0f / row_l[i];
        const float o0 = acc_o[i][0] * inv, o1 = acc_o[i][1] * inv;
        const float o2 = acc_o[i][2] * inv, o3 = acc_o[i][3] * inv;
        const uint32_t h0 = cvt_bf16x2(o1, o0);
        const uint32_t h1 = cvt_bf16x2(o3, o2);
        const uint32_t l0 = cvt_bf16x2(o1 - __uint_as_float(h0 & 0xFFFF0000u),
                                       o0 - __uint_as_float(h0 << 16));
        const uint32_t l1 = cvt_bf16x2(o3 - __uint_as_float(h1 & 0xFFFF0000u),
                                       o2 - __uint_as_float(h1 << 16));
        const size_t w2 = (((size_t)(b * SEQ + n)) * DIM + h * HD + tx * 4) >> 2;
        reinterpret_cast<uint2*>(Oh)[w2] = make_uint2(h0, h1);
        reinterpret_cast<uint2*>(Ol)[w2] = make_uint2(l0, l1);
    }
}

// ---------------- launch ----------------
extern "C" void kernel_launch(void* const* d_in, const int* in_sizes, int n_in,
                              void* d_out, int out_size)
{
    const float* x     = (const float*)d_in[0];
    const float* ln1_g = (const float*)d_in[1];
    const float* ln1_b = (const float*)d_in[2];
    const float* Wqkv  = (const float*)d_in[3];
    const float* Wproj = (const float*)d_in[4];
    const float* bproj = (const float*)d_in[5];
    const float* ln2_g = (const float*)d_in[6];
    const float* ln2_b = (const float*)d_in[7];
    const float* W1    = (const float*)d_in[8];
    const float* b1    = (const float*)d_in[9];
    const float* W2    = (const float*)d_in[10];
    const float* b2    = (const float*)d_in[11];
    float* out = (float*)d_out;

    void* p_arena;
    cudaGetSymbolAddress(&p_arena, g_arena);
    uint32_t* a = (uint32_t*)p_arena;
    float*    qkvb = (float*)a;                 a += QKV_W;
    float*    x2b  = (float*)a;                 a += X2_W;
    uint32_t* hph  = a;                         a += HP_W;   // h/O hi plane
    uint32_t* hpl  = a;                         a += HP_W;   // h/O lo plane
    uint32_t* mph  = a;                         a += MP_W;
    uint32_t* mpl  = a;                         a += MP_W;
    uint16_t* wqh  = (uint16_t*)a;              a += WQKV_W;
    uint16_t* wql  = (uint16_t*)a;              a += WQKV_W;
    uint16_t* wph  = (uint16_t*)a;              a += WPROJ_W;
    uint16_t* wpl  = (uint16_t*)a;              a += WPROJ_W;
    uint16_t* w1h  = (uint16_t*)a;              a += W1_W;
    uint16_t* w1l  = (uint16_t*)a;              a += W1_W;
    uint16_t* w2h  = (uint16_t*)a;              a += W2_W;
    uint16_t* w2l  = (uint16_t*)a;

    cudaFuncSetAttribute(fattn_kernel,
                         cudaFuncAttributeMaxDynamicSharedMemorySize, FA_SMEM);
    cudaFuncSetAttribute(tcgemm_kernel<false,false,false,false>,
                         cudaFuncAttributeMaxDynamicSharedMemorySize, GEMM_SMEM);
    cudaFuncSetAttribute(tcgemm_kernel<true,false,true,false>,
                         cudaFuncAttributeMaxDynamicSharedMemorySize, GEMM_SMEM);
    cudaFuncSetAttribute(tcgemm_kernel<true,true,false,true>,
                         cudaFuncAttributeMaxDynamicSharedMemorySize, GEMM_SMEM);

    const int MT = (NTOK + 127) / 128;  // 289

    // 0. split weights into bf16 planes (transposed to [N][K])
    splitw_kernel<<<(int)(((size_t)QKVD*DIM + 255)/256), 256>>>(Wqkv, wqh, wql, DIM, QKVD);
    splitw_kernel<<<(int)(((size_t)DIM*DIM + 255)/256), 256>>>(Wproj, wph, wpl, DIM, DIM);
    splitw_kernel<<<(int)(((size_t)HIDDEN*DIM + 255)/256), 256>>>(W1, w1h, w1l, DIM, HIDDEN);
    splitw_kernel<<<(int)(((size_t)DIM*HIDDEN + 255)/256), 256>>>(W2, w2h, w2l, HIDDEN, DIM);

    // 1. h planes = split(LN1(x))
    lnx2_kernel<<<NTOK, 192>>>(x, ln1_g, ln1_b, hph, hpl);
    // 2. qkv = h @ Wqkv (fp32 out)
    tcgemm_kernel<false,false,false,false><<<dim3(QKVD/256, MT), 256, GEMM_SMEM>>>(
        (const uint16_t*)hph, (const uint16_t*)hpl, wqh, wql,
        nullptr, nullptr, qkvb, nullptr, nullptr, NTOK, QKVD, DIM);
    // 3. attention -> O planes (reuse h planes)
    fattn_kernel<<<dim3(10, BATCH*HEADS), 256, FA_SMEM>>>(qkvb, hph, hpl);
    // 4. x2 = x + O @ Wproj + bproj
    tcgemm_kernel<true,false,true,false><<<dim3(DIM/256, MT), 256, GEMM_SMEM>>>(
        (const uint16_t*)hph, (const uint16_t*)hpl, wph, wpl,
        bproj, x, x2b, nullptr, nullptr, NTOK, DIM, DIM);
    // 5. h planes = split(LN2(x2))
    lnx2_kernel<<<NTOK, 192>>>(x2b, ln2_g, ln2_b, hph, hpl);
    // 6. m planes = split(gelu(h @ W1 + b1))
    tcgemm_kernel<true,true,false,true><<<dim3(HIDDEN/256, MT), 256, GEMM_SMEM>>>(
        (const uint16_t*)hph, (const uint16_t*)hpl, w1h, w1l,
        b1, nullptr, nullptr, mph, mpl, NTOK, HIDDEN, DIM);
    // 7. out = x2 + m @ W2 + b2
    tcgemm_kernel<true,false,true,false><<<dim3(DIM/256, MT), 256, GEMM_SMEM>>>(
        (const uint16_t*)mph, (const uint16_t*)mpl, w2h, w2l,
        b2, x2b, out, nullptr, nullptr, NTOK, DIM, HIDDEN);
}

// round 15
// speedup vs baseline: 1.4106x; 1.4106x over previous
#include <cuda_runtime.h>
#include <math.h>
#include <stdint.h>

#define DIM      768
#define HEADS    12
#define HD       64
#define HIDDEN   3072
#define SEQ      577
#define BATCH    64
#define NTOK     (BATCH*SEQ)  // 36928
#define QKVD     (3*DIM)      // 2304

// ---------------- single scratch arena (overlaid buffers) ----------------
#define ARENA_FLOATS ((size_t)NTOK * DIM * 2 + (size_t)NTOK * HIDDEN)
__device__ __align__(16) float g_arena[ARENA_FLOATS];

// ---------------- helpers ----------------
__device__ __forceinline__ uint32_t smem_u32(const void* p) {
    uint32_t a;
    asm("{ .reg .u64 t; cvta.to.shared.u64 t, %1; cvt.u32.u64 %0, t; }"
        : "=r"(a) : "l"(p));
    return a;
}
// word = bf16(hi)<<16 | bf16(lo), RNE
__device__ __forceinline__ uint32_t cvt_bf16x2(float hi, float lo) {
    uint32_t r;
    asm("cvt.rn.bf16x2.f32 %0, %1, %2;" : "=r"(r) : "f"(hi), "f"(lo));
    return r;
}

#define LDSM4(r0, r1, r2, r3, addr) \
    asm volatile("ldmatrix.sync.aligned.m8n8.x4.shared.b16 {%0,%1,%2,%3}, [%4];" \
                 : "=r"(r0), "=r"(r1), "=r"(r2), "=r"(r3) : "r"(addr))
#define LDSM4T(r0, r1, r2, r3, addr) \
    asm volatile("ldmatrix.sync.aligned.m8n8.x4.trans.shared.b16 {%0,%1,%2,%3}, [%4];" \
                 : "=r"(r0), "=r"(r1), "=r"(r2), "=r"(r3) : "r"(addr))

#define MMA_BF16(d, a, b) \
    asm volatile("mma.sync.aligned.m16n8k16.row.col.f32.bf16.bf16.f32 " \
                 "{%0,%1,%2,%3}, {%4,%5,%6,%7}, {%8,%9}, {%0,%1,%2,%3};" \
                 : "+f"((d)[0]), "+f"((d)[1]), "+f"((d)[2]), "+f"((d)[3]) \
                 : "r"((a)[0]), "r"((a)[1]), "r"((a)[2]), "r"((a)[3]), \
                   "r"((b)[0]), "r"((b)[1]))

// ============ bf16-split tensor-core GEMM (R12 winner, verbatim) ============
#define PITCHB   208
#define ATILE    (128 * PITCHB)
#define BTILE    (256 * PITCHB)
#define BUFB     (ATILE + BTILE)
#define GEMM_SMEM (2 * BUFB)

template<bool BIAS, bool GELU, bool RES>
__global__ __launch_bounds__(256, 1) void tcgemm_kernel(
    const float* __restrict__ A, const float* __restrict__ B,
    const float* __restrict__ bias, const float* __restrict__ res,
    float* __restrict__ C, int M, int N, int K)
{
    extern __shared__ char smem[];
    const uint32_t sb = smem_u32(smem);
    const int tid  = threadIdx.x;
    const int lane = tid & 31;
    const int wid  = tid >> 5;
    const int wr = wid >> 2, wc = wid & 3;
    const int m0w = wr * 64, n0w = wc * 64;

    const int m0 = blockIdx.y * 128, col0 = blockIdx.x * 256;

    const int arow = tid >> 1, aseg = tid & 1;
    const int gar = m0 + arow;
    const bool aval = (gar < M);
    const float* Ap = A + (size_t)gar * K + aseg * 16;
    char* sArow = smem + arow * PITCHB + aseg * 96;

    const int bn = tid;
    const float* Bp = B + col0 + bn;
    char* sBrow = smem + ATILE + bn * PITCHB;

    float dacc[32][4];
    #pragma unroll
    for (int t = 0; t < 32; t++)
        #pragma unroll
        for (int c = 0; c < 4; c++) dacc[t][c] = 0.f;

    const int NBLK = K >> 5;

    auto store_tiles = [&](int bufo, const float4 a4[4], const float bl[32]) {
        char* dst = sArow + bufo;
        #pragma unroll
        for (int q = 0; q < 4; q++) {
            const float v[4] = {a4[q].x, a4[q].y, a4[q].z, a4[q].w};
            #pragma unroll
            for (int pp = 0; pp < 2; pp++) {
                const float v0 = v[pp*2], v1 = v[pp*2+1];
                const uint32_t h01 = cvt_bf16x2(v1, v0);
                const float f0h = __uint_as_float(h01 << 16);
                const float f1h = __uint_as_float(h01 & 0xFFFF0000u);
                const uint32_t l01 = cvt_bf16x2(v1 - f1h, v0 - f0h);
                uint32_t* w = reinterpret_cast<uint32_t*>(dst + (q*2 + pp) * 12);
                w[0] = __byte_perm(h01, h01, 0x1010);
                w[1] = __byte_perm(l01, h01, 0x7610);
                w[2] = __byte_perm(l01, h01, 0x3276);
            }
        }
        char* dstb = sBrow + bufo;
        #pragma unroll
        for (int j = 0; j < 16; j++) {
            const float v0 = bl[2*j], v1 = bl[2*j+1];
            const uint32_t h01 = cvt_bf16x2(v1, v0);
            const float f0h = __uint_as_float(h01 << 16);
            const float f1h = __uint_as_float(h01 & 0xFFFF0000u);
            const uint32_t l01 = cvt_bf16x2(v1 - f1h, v0 - f0h);
            uint32_t* w = reinterpret_cast<uint32_t*>(dstb + j * 12);
            w[0] = __byte_perm(l01, h01, 0x1054);
            w[1] = h01;
            w[2] = __byte_perm(l01, h01, 0x7632);
        }
    };

    {
        float4 a4[4]; float bl[32];
        #pragma unroll
        for (int q = 0; q < 4; q++)
            a4[q] = aval ? *reinterpret_cast<const float4*>(Ap + q * 4)
                         : make_float4(0.f, 0.f, 0.f, 0.f);
        #pragma unroll
        for (int i = 0; i < 32; i++) bl[i] = Bp[(size_t)i * N];
        store_tiles(0, a4, bl);
    }
    __syncthreads();

    int buf = 0;
    for (int blk = 0; blk < NBLK; blk++) {
        float4 a4[4]; float bl[32];
        const bool more = (blk + 1 < NBLK);
        if (more) {
            const float* Apn = Ap + (blk + 1) * 32;
            const float* Bpn = Bp + (size_t)(blk + 1) * 32 * N;
            #pragma unroll
            for (int q = 0; q < 4; q++)
                a4[q] = aval ? *reinterpret_cast<const float4*>(Apn + q * 4)
                             : make_float4(0.f, 0.f, 0.f, 0.f);
            #pragma unroll
            for (int i = 0; i < 32; i++) bl[i] = Bpn[(size_t)i * N];
        }

        const uint32_t sA  = sb + buf * BUFB;
        const uint32_t sBB = sA + ATILE;
        const uint32_t aAddrBase = sA + (uint32_t)(m0w + (lane & 15)) * PITCHB
                                      + ((lane >> 4) * 8) * 2;
        const int g = lane >> 3;
        const uint32_t bAddrBase = sBB + (uint32_t)(n0w + ((g >> 1) * 8) + (lane & 7)) * PITCHB
                                       + ((g & 1) * 8) * 2;
        #pragma unroll
        for (int kc = 0; kc < 6; kc++) {
            uint32_t af[4][4], bfr[8][2];
            #pragma unroll
            for (int mi = 0; mi < 4; mi++)
                LDSM4(af[mi][0], af[mi][1], af[mi][2], af[mi][3],
                      aAddrBase + (uint32_t)mi * 16 * PITCHB + kc * 32);
            #pragma unroll
            for (int p = 0; p < 4; p++)
                LDSM4(bfr[2*p][0], bfr[2*p][1], bfr[2*p+1][0], bfr[2*p+1][1],
                      bAddrBase + (uint32_t)p * 16 * PITCHB + kc * 32);
            #pragma unroll
            for (int mi = 0; mi < 4; mi++)
                #pragma unroll
                for (int nt = 0; nt < 8; nt++)
                    MMA_BF16(dacc[mi * 8 + nt], af[mi], bfr[nt]);
        }

        if (more) {
            store_tiles((buf ^ 1) * BUFB, a4, bl);
            __syncthreads();
            buf ^= 1;
        }
    }

    #pragma unroll
    for (int mi = 0; mi < 4; mi++) {
        const int r0 = m0 + m0w + mi * 16 + (lane >> 2);
        #pragma unroll
        for (int nt = 0; nt < 8; nt++) {
            const int c = col0 + n0w + nt * 8 + (lane & 3) * 2;
            const float* d = dacc[mi * 8 + nt];
            float b0 = 0.f, b1 = 0.f;
            if (BIAS) { b0 = bias[c]; b1 = bias[c + 1]; }
            #pragma unroll
            for (int half = 0; half < 2; half++) {
                const int r = r0 + half * 8;
                if (r >= M) continue;
                float v0 = d[half * 2 + 0] + b0;
                float v1 = d[half * 2 + 1] + b1;
                if (GELU) {
                    v0 = 0.5f * v0 * (1.0f + erff(v0 * 0.70710678118654752f));
                    v1 = 0.5f * v1 * (1.0f + erff(v1 * 0.70710678118654752f));
                }
                if (RES) {
                    const float2 rv = *reinterpret_cast<const float2*>(
                        res + (size_t)r * N + c);
                    v0 += rv.x; v1 += rv.y;
                }
                *reinterpret_cast<float2*>(C + (size_t)r * N + c) =
                    make_float2(v0, v1);
            }
        }
    }
}

// ---------------- LayerNorm (R12) ----------------
__global__ __launch_bounds__(256) void ln_kernel(
    const float* __restrict__ x, const float* __restrict__ g,
    const float* __restrict__ b, float* __restrict__ out)
{
    const size_t t = blockIdx.x;
    const float* xr = x + t * DIM;
    const int tid = threadIdx.x;

    float v0 = xr[tid], v1 = xr[tid + 256], v2 = xr[tid + 512];
    float s  = v0 + v1 + v2;
    float ss = v0*v0 + v1*v1 + v2*v2;

    __shared__ float red[16];
    __shared__ float stat[2];
    #pragma unroll
    for (int o = 16; o; o >>= 1) {
        s  += __shfl_xor_sync(0xffffffffu, s,  o);
        ss += __shfl_xor_sync(0xffffffffu, ss, o);
    }
    if ((tid & 31) == 0) { red[tid >> 5] = s; red[(tid >> 5) + 8] = ss; }
    __syncthreads();
    if (tid == 0) {
        float a = 0.f, c = 0.f;
        #pragma unroll
        for (int i = 0; i < 8; i++) { a += red[i]; c += red[i + 8]; }
        float mu = a * (1.0f / DIM);
        float var = c * (1.0f / DIM) - mu * mu;
        stat[0] = mu;
        stat[1] = rsqrtf(var + 1e-5f);
    }
    __syncthreads();
    const float mu = stat[0], inv = stat[1];
    float* orow = out + t * DIM;
    orow[tid      ] = (v0 - mu) * inv * g[tid      ] + b[tid      ];
    orow[tid + 256] = (v1 - mu) * inv * g[tid + 256] + b[tid + 256];
    orow[tid + 512] = (v2 - mu) * inv * g[tid + 512] + b[tid + 512];
}

// ============ tensor-core flash attention ============
// 64 q-rows per block, 8 warps: wr = wid&3 (m16), wc = wid>>2 (key half of 32).
// Q/K/V in smem as hi/lo bf16 planes, pitch 144 B.
// QK: 3-pass split mma; softmax in C-layout regs; PV: P regs -> A frags, V via
// ldmatrix.trans, 3-pass split; O cross-half reduce in smem at the end.
#define FPITCH   144
#define FPL      (64 * FPITCH)       // 9216 per plane
#define FQH 0
#define FQL (FPL)
#define FKH (2*FPL)
#define FKL (3*FPL)
#define FVH (4*FPL)
#define FVL (5*FPL)
#define FSMAX (6*FPL)                // 55296: [2][4][16] floats = 512 B
#define FSSUM (FSMAX + 512)
#define FLSUM (FSSUM + 512)          // 64 floats
#define FA2_SMEM (FLSUM + 256)       // 56832

__global__ __launch_bounds__(256, 2) void fattn2_kernel(
    const float* __restrict__ qkv, float* __restrict__ O)
{
    extern __shared__ char sm[];
    const uint32_t sb = smem_u32(sm);
    const int tid = threadIdx.x;
    const int lane = tid & 31;
    const int wid = tid >> 5;
    const int wr = wid & 3, wc = wid >> 2;
    const int q4 = lane & 3, r4 = lane >> 2;       // quad col, quad row

    const int bh = blockIdx.y;
    const int b = bh / HEADS, h = bh % HEADS;
    const int n0 = blockIdx.x * 64;
    const float* qb = qkv + (size_t)b * SEQ * QKVD + h * HD;
    const float* kb = qb + DIM;
    const float* vb = qb + 2 * DIM;

    const int lr = tid >> 2;            // loader row 0..63
    const int lc = (tid & 3) * 16;      // loader col 0,16,32,48

    // convert+store one float4 into hi/lo planes at (row, col elements ce..ce+3)
    auto cvst = [&](uint32_t ph, uint32_t pl, float4 v, int row, int ce) {
        const uint32_t h0 = cvt_bf16x2(v.y, v.x);
        const uint32_t l0 = cvt_bf16x2(v.y - __uint_as_float(h0 & 0xFFFF0000u),
                                       v.x - __uint_as_float(h0 << 16));
        const uint32_t h1 = cvt_bf16x2(v.w, v.z);
        const uint32_t l1 = cvt_bf16x2(v.w - __uint_as_float(h1 & 0xFFFF0000u),
                                       v.z - __uint_as_float(h1 << 16));
        const uint32_t off = row * FPITCH + ce * 2;
        asm volatile("st.shared.v2.b32 [%0], {%1,%2};" :: "r"(sb + ph + off), "r"(h0), "r"(h1));
        asm volatile("st.shared.v2.b32 [%0], {%1,%2};" :: "r"(sb + pl + off), "r"(l0), "r"(l1));
    };

    // ---- load Q (scaled by 0.125) ----
    {
        const int n = n0 + lr;
        const float4* src = (n < SEQ)
            ? reinterpret_cast<const float4*>(qb + (size_t)n * QKVD + lc) : nullptr;
        #pragma unroll
        for (int c4 = 0; c4 < 4; c4++) {
            float4 v = src ? src[c4] : make_float4(0.f,0.f,0.f,0.f);
            v.x *= 0.125f; v.y *= 0.125f; v.z *= 0.125f; v.w *= 0.125f;
            cvst(FQH, FQL, v, lr, lc + c4 * 4);
        }
    }

    float o[8][4];
    float mA = -1e30f, mB = -1e30f, lA = 0.f, lB = 0.f;
    #pragma unroll
    for (int t = 0; t < 8; t++)
        #pragma unroll
        for (int c = 0; c < 4; c++) o[t][c] = 0.f;

    float* smax = reinterpret_cast<float*>(sm + FSMAX);
    float* ssum = reinterpret_cast<float*>(sm + FSSUM);
    const int sidx = (wc * 4 + wr) * 16;
    const int oidx = ((wc ^ 1) * 4 + wr) * 16;

    for (int k0 = 0; k0 < SEQ; k0 += 64) {
        __syncthreads();   // prior iteration's smem reads complete
        // ---- load K,V tile ----
        {
            const int m = k0 + lr;
            const float4* sk = (m < SEQ)
                ? reinterpret_cast<const float4*>(kb + (size_t)m * QKVD + lc) : nullptr;
            const float4* sv = (m < SEQ)
                ? reinterpret_cast<const float4*>(vb + (size_t)m * QKVD + lc) : nullptr;
            #pragma unroll
            for (int c4 = 0; c4 < 4; c4++) {
                float4 v = sk ? sk[c4] : make_float4(0.f,0.f,0.f,0.f);
                cvst(FKH, FKL, v, lr, lc + c4 * 4);
                float4 w = sv ? sv[c4] : make_float4(0.f,0.f,0.f,0.f);
                cvst(FVH, FVL, w, lr, lc + c4 * 4);
            }
        }
        __syncthreads();

        // ---- QK^T: S[16 x 32] per warp, 3-pass split ----
        float s[4][4];
        #pragma unroll
        for (int t = 0; t < 4; t++)
            #pragma unroll
            for (int c = 0; c < 4; c++) s[t][c] = 0.f;

        const uint32_t qAddr = sb + (uint32_t)(16 * wr + (lane & 15)) * FPITCH
                                  + (lane >> 4) * 16;
        const int g = lane >> 3;
        const uint32_t kAddr = sb + FKH
            + (uint32_t)(wc * 32 + (g >> 1) * 8 + (lane & 7)) * FPITCH
            + (g & 1) * 16;

        #pragma unroll
        for (int ks = 0; ks < 4; ks++) {
            uint32_t qh[4], ql[4], kh[8], kl[8];
            LDSM4(qh[0], qh[1], qh[2], qh[3], qAddr + FQH + ks * 32);
            LDSM4(ql[0], ql[1], ql[2], ql[3], qAddr + FQL + ks * 32);
            #pragma unroll
            for (int t2 = 0; t2 < 2; t2++) {
                LDSM4(kh[t2*4], kh[t2*4+1], kh[t2*4+2], kh[t2*4+3],
                      kAddr + (uint32_t)t2 * 16 * FPITCH + ks * 32);
                LDSM4(kl[t2*4], kl[t2*4+1], kl[t2*4+2], kl[t2*4+3],
                      kAddr + (FKL - FKH) + (uint32_t)t2 * 16 * FPITCH + ks * 32);
            }
            #pragma unroll
            for (int t = 0; t < 4; t++) {
                MMA_BF16(s[t], qh, &kh[t*2]);
                MMA_BF16(s[t], qh, &kl[t*2]);
                MMA_BF16(s[t], ql, &kh[t*2]);
            }
        }

        // ---- mask OOB keys ----
        #pragma unroll
        for (int t = 0; t < 4; t++) {
            const int key0 = k0 + wc * 32 + t * 8 + 2 * q4;
            if (key0 >= SEQ)     { s[t][0] = -1e30f; s[t][2] = -1e30f; }
            if (key0 + 1 >= SEQ) { s[t][1] = -1e30f; s[t][3] = -1e30f; }
        }

        // ---- local row max (warp's 32 cols) ----
        float tmA = -1e30f, tmB = -1e30f;
        #pragma unroll
        for (int t = 0; t < 4; t++) {
            tmA = fmaxf(tmA, fmaxf(s[t][0], s[t][1]));
            tmB = fmaxf(tmB, fmaxf(s[t][2], s[t][3]));
        }
        tmA = fmaxf(tmA, __shfl_xor_sync(0xffffffffu, tmA, 1));
        tmA = fmaxf(tmA, __shfl_xor_sync(0xffffffffu, tmA, 2));
        tmB = fmaxf(tmB, __shfl_xor_sync(0xffffffffu, tmB, 1));
        tmB = fmaxf(tmB, __shfl_xor_sync(0xffffffffu, tmB, 2));
        if (q4 == 0) { smax[sidx + r4] = tmA; smax[sidx + r4 + 8] = tmB; }
        __syncthreads();
        tmA = fmaxf(tmA, smax[oidx + r4]);
        tmB = fmaxf(tmB, smax[oidx + r4 + 8]);

        const float nmA = fmaxf(mA, tmA), nmB = fmaxf(mB, tmB);
        const float fA = __expf(mA - nmA), fB = __expf(mB - nmB);
        mA = nmA; mB = nmB;

        // ---- exp + local sums ----
        float suA = 0.f, suB = 0.f;
        #pragma unroll
        for (int t = 0; t < 4; t++) {
            s[t][0] = __expf(s[t][0] - nmA); suA += s[t][0];
            s[t][1] = __expf(s[t][1] - nmA); suA += s[t][1];
            s[t][2] = __expf(s[t][2] - nmB); suB += s[t][2];
            s[t][3] = __expf(s[t][3] - nmB); suB += s[t][3];
        }
        suA += __shfl_xor_sync(0xffffffffu, suA, 1);
        suA += __shfl_xor_sync(0xffffffffu, suA, 2);
        suB += __shfl_xor_sync(0xffffffffu, suB, 1);
        suB += __shfl_xor_sync(0xffffffffu, suB, 2);
        if (q4 == 0) { ssum[sidx + r4] = suA; ssum[sidx + r4 + 8] = suB; }
        __syncthreads();
        lA = lA * fA + suA + ssum[oidx + r4];
        lB = lB * fB + suB + ssum[oidx + r4 + 8];

        // ---- rescale O ----
        #pragma unroll
        for (int t = 0; t < 8; t++) {
            o[t][0] *= fA; o[t][1] *= fA; o[t][2] *= fB; o[t][3] *= fB;
        }

        // ---- PV: O += P V  (warp's 32-key slice, 3-pass split) ----
        const uint32_t vAddr = sb + FVH
            + (uint32_t)(wc * 32 + (lane & 7) + ((lane >> 3) & 1) * 8) * FPITCH
            + (lane >> 4) * 16;
        #pragma unroll
        for (int ks = 0; ks < 2; ks++) {
            // P A-fragments from s tiles 2ks, 2ks+1
            uint32_t ph[4], pl[4];
            #pragma unroll
            for (int half = 0; half < 2; half++) {
                const float* sj = s[2 * ks + half];
                const uint32_t hA = cvt_bf16x2(sj[1], sj[0]);
                const uint32_t lAw = cvt_bf16x2(
                    sj[1] - __uint_as_float(hA & 0xFFFF0000u),
                    sj[0] - __uint_as_float(hA << 16));
                const uint32_t hB = cvt_bf16x2(sj[3], sj[2]);
                const uint32_t lBw = cvt_bf16x2(
                    sj[3] - __uint_as_float(hB & 0xFFFF0000u),
                    sj[2] - __uint_as_float(hB << 16));
                ph[half * 2]     = hA;  ph[half * 2 + 1] = hB;
                pl[half * 2]     = lAw; pl[half * 2 + 1] = lBw;
            }
            // reorder: A frag = {a0(rowA,k0-7), a1(rowB,k0-7), a2(rowA,k8-15), a3(rowB,k8-15)}
            // built above as [tile0 rowA, tile0 rowB, tile1 rowA, tile1 rowB] — matches.

            #pragma unroll
            for (int dp = 0; dp < 4; dp++) {
                uint32_t vh[4], vl[4];
                LDSM4T(vh[0], vh[1], vh[2], vh[3],
                       vAddr + (uint32_t)(ks * 16) * FPITCH + dp * 32);
                LDSM4T(vl[0], vl[1], vl[2], vl[3],
                       vAddr + (FVL - FVH) + (uint32_t)(ks * 16) * FPITCH + dp * 32);
                const int dt = dp * 2;
                MMA_BF16(o[dt], ph, &vh[0]);
                MMA_BF16(o[dt], ph, &vl[0]);
                MMA_BF16(o[dt], pl, &vh[0]);
                MMA_BF16(o[dt + 1], ph, &vh[2]);
                MMA_BF16(o[dt + 1], ph, &vl[2]);
                MMA_BF16(o[dt + 1], pl, &vh[2]);
            }
        }
    }

    __syncthreads();   // all compute done; reuse Q/K smem for O exchange

    // row sums to smem
    float* lsum = reinterpret_cast<float*>(sm + FLSUM);
    if (wc == 0 && q4 == 0) {
        lsum[wr * 16 + r4] = lA;
        lsum[wr * 16 + r4 + 8] = lB;
    }
    // O partials to smem [row][64] f32 per half
    float* obuf = reinterpret_cast<float*>(sm) + wc * 4096;
    {
        const int rA = wr * 16 + r4, rB = rA + 8;
        #pragma unroll
        for (int t = 0; t < 8; t++) {
            const int c = t * 8 + 2 * q4;
            obuf[rA * 64 + c]     = o[t][0];
            obuf[rA * 64 + c + 1] = o[t][1];
            obuf[rB * 64 + c]     = o[t][2];
            obuf[rB * 64 + c + 1] = o[t][3];
        }
    }
    __syncthreads();

    // combine halves, normalize, write
    {
        const int n = n0 + lr;
        if (n < SEQ) {
            const float inv = 1.0f / lsum[lr];
            float* b0 = reinterpret_cast<float*>(sm) + lr * 64 + lc;
            float* b1 = b0 + 4096;
            float* dst = O + ((size_t)(b * SEQ + n)) * DIM + h * HD + lc;
            #pragma unroll
            for (int c4 = 0; c4 < 4; c4++) {
                float4 u = *reinterpret_cast<float4*>(b0 + c4 * 4);
                float4 v = *reinterpret_cast<float4*>(b1 + c4 * 4);
                float4 r = make_float4((u.x + v.x) * inv, (u.y + v.y) * inv,
                                       (u.z + v.z) * inv, (u.w + v.w) * inv);
                *reinterpret_cast<float4*>(dst + c4 * 4) = r;
            }
        }
    }
}

// ---------------- launch ----------------
extern "C" void kernel_launch(void* const* d_in, const int* in_sizes, int n_in,
                              void* d_out, int out_size)
{
    const float* x     = (const float*)d_in[0];
    const float* ln1_g = (const float*)d_in[1];
    const float* ln1_b = (const float*)d_in[2];
    const float* Wqkv  = (const float*)d_in[3];
    const float* Wproj = (const float*)d_in[4];
    const float* bproj = (const float*)d_in[5];
    const float* ln2_g = (const float*)d_in[6];
    const float* ln2_b = (const float*)d_in[7];
    const float* W1    = (const float*)d_in[8];
    const float* b1    = (const float*)d_in[9];
    const float* W2    = (const float*)d_in[10];
    const float* b2    = (const float*)d_in[11];
    float* out = (float*)d_out;

    void* p_arena;
    cudaGetSymbolAddress(&p_arena, g_arena);
    float* arena = (float*)p_arena;
    float* h_buf = arena;
    float* x2buf = arena + (size_t)NTOK * DIM;
    float* qkvb  = arena + (size_t)NTOK * DIM * 2;
    float* mbuf  = qkvb;

    cudaFuncSetAttribute(fattn2_kernel,
                         cudaFuncAttributeMaxDynamicSharedMemorySize, FA2_SMEM);
    cudaFuncSetAttribute(tcgemm_kernel<false,false,false>,
                         cudaFuncAttributeMaxDynamicSharedMemorySize, GEMM_SMEM);
    cudaFuncSetAttribute(tcgemm_kernel<true,false,true>,
                         cudaFuncAttributeMaxDynamicSharedMemorySize, GEMM_SMEM);
    cudaFuncSetAttribute(tcgemm_kernel<true,true,false>,
                         cudaFuncAttributeMaxDynamicSharedMemorySize, GEMM_SMEM);

    const int MT = (NTOK + 127) / 128;  // 289

    // 1. h = LN1(x)
    ln_kernel<<<NTOK, 256>>>(x, ln1_g, ln1_b, h_buf);
    // 2. qkv = h @ Wqkv
    tcgemm_kernel<false,false,false><<<dim3(QKVD/256, MT), 256, GEMM_SMEM>>>(
        h_buf, Wqkv, nullptr, nullptr, qkvb, NTOK, QKVD, DIM);
    // 3. tensor-core attention -> h_buf
    fattn2_kernel<<<dim3(10, BATCH*HEADS), 256, FA2_SMEM>>>(qkvb, h_buf);
    // 4. x2 = x + O @ Wproj + bproj
    tcgemm_kernel<true,false,true><<<dim3(DIM/256, MT), 256, GEMM_SMEM>>>(
        h_buf, Wproj, bproj, x, x2buf, NTOK, DIM, DIM);
    // 5. h = LN2(x2)
    ln_kernel<<<NTOK, 256>>>(x2buf, ln2_g, ln2_b, h_buf);
    // 6. m = gelu(h @ W1 + b1)
    tcgemm_kernel<true,true,false><<<dim3(HIDDEN/256, MT), 256, GEMM_SMEM>>>(
        h_buf, W1, b1, nullptr, mbuf, NTOK, HIDDEN, DIM);
    // 7. out = x2 + m @ W2 + b2
    tcgemm_kernel<true,false,true><<<dim3(DIM/256, MT), 256, GEMM_SMEM>>>(
        mbuf, W2, b2, x2buf, out, NTOK, DIM, HIDDEN);
}

// round 16
// speedup vs baseline: 1.7349x; 1.2298x over previous
#include <cuda_runtime.h>
#include <cuda_fp16.h>
#include <math.h>
#include <stdint.h>

#define DIM      768
#define HEADS    12
#define HD       64
#define HIDDEN   3072
#define SEQ      577
#define BATCH    64
#define NTOK     (BATCH*SEQ)  // 36928
#define QKVD     (3*DIM)      // 2304

// ---------------- single scratch arena (overlaid buffers) ----------------
#define ARENA_FLOATS ((size_t)NTOK * DIM * 2 + (size_t)NTOK * HIDDEN)
__device__ __align__(16) float g_arena[ARENA_FLOATS];

// ---------------- helpers ----------------
__device__ __forceinline__ uint32_t smem_u32(const void* p) {
    uint32_t a;
    asm("{ .reg .u64 t; cvta.to.shared.u64 t, %1; cvt.u32.u64 %0, t; }"
        : "=r"(a) : "l"(p));
    return a;
}
// word = bf16(hi)<<16 | bf16(lo), RNE
__device__ __forceinline__ uint32_t cvt_bf16x2(float hi, float lo) {
    uint32_t r;
    asm("cvt.rn.bf16x2.f32 %0, %1, %2;" : "=r"(r) : "f"(hi), "f"(lo));
    return r;
}
// word = f16(hi)<<16 | f16(lo), RNE
__device__ __forceinline__ uint32_t cvt_f16x2(float hi, float lo) {
    uint32_t r;
    asm("cvt.rn.f16x2.f32 %0, %1, %2;" : "=r"(r) : "f"(hi), "f"(lo));
    return r;
}

#define LDSM4(r0, r1, r2, r3, addr) \
    asm volatile("ldmatrix.sync.aligned.m8n8.x4.shared.b16 {%0,%1,%2,%3}, [%4];" \
                 : "=r"(r0), "=r"(r1), "=r"(r2), "=r"(r3) : "r"(addr))
#define LDSM4T(r0, r1, r2, r3, addr) \
    asm volatile("ldmatrix.sync.aligned.m8n8.x4.trans.shared.b16 {%0,%1,%2,%3}, [%4];" \
                 : "=r"(r0), "=r"(r1), "=r"(r2), "=r"(r3) : "r"(addr))

#define MMA_BF16(d, a, b) \
    asm volatile("mma.sync.aligned.m16n8k16.row.col.f32.bf16.bf16.f32 " \
                 "{%0,%1,%2,%3}, {%4,%5,%6,%7}, {%8,%9}, {%0,%1,%2,%3};" \
                 : "+f"((d)[0]), "+f"((d)[1]), "+f"((d)[2]), "+f"((d)[3]) \
                 : "r"((a)[0]), "r"((a)[1]), "r"((a)[2]), "r"((a)[3]), \
                   "r"((b)[0]), "r"((b)[1]))
#define MMA_F16(d, a, b) \
    asm volatile("mma.sync.aligned.m16n8k16.row.col.f32.f16.f16.f32 " \
                 "{%0,%1,%2,%3}, {%4,%5,%6,%7}, {%8,%9}, {%0,%1,%2,%3};" \
                 : "+f"((d)[0]), "+f"((d)[1]), "+f"((d)[2]), "+f"((d)[3]) \
                 : "r"((a)[0]), "r"((a)[1]), "r"((a)[2]), "r"((a)[3]), \
                   "r"((b)[0]), "r"((b)[1]))

// ===== fp16 2-term split GEMM: 128x256 tile, k-block 32 (R12 skeleton) =====
// A [M,K] fp32, B [K,N] fp32. Slots per real k: A=[ah,ah], B=[bh,bl]
// => slot-aligned products ah*bh + ah*bl. 4 k16 chunks per 32 real k.
#define PITCHB   144                    // 64 slots * 2B + 16 pad
#define ATILE    (128 * PITCHB)         // 18432
#define BTILE    (256 * PITCHB)         // 36864
#define BUFB     (ATILE + BTILE)        // 55296
#define GEMM_SMEM (2 * BUFB)            // 110592

template<bool BIAS, bool GELU, bool RES>
__global__ __launch_bounds__(256, 1) void tcgemm_kernel(
    const float* __restrict__ A, const float* __restrict__ B,
    const float* __restrict__ bias, const float* __restrict__ res,
    float* __restrict__ C, int M, int N, int K)
{
    extern __shared__ char smem[];
    const uint32_t sb = smem_u32(smem);
    const int tid  = threadIdx.x;
    const int lane = tid & 31;
    const int wid  = tid >> 5;
    const int wr = wid >> 2, wc = wid & 3;        // warp grid 2 x 4
    const int m0w = wr * 64, n0w = wc * 64;       // warp tile 64 x 64

    const int m0 = blockIdx.y * 128, col0 = blockIdx.x * 256;

    // A loader: row = tid/2, seg covers 16 floats -> 32 slots = 64 B
    const int arow = tid >> 1, aseg = tid & 1;
    const int gar = m0 + arow;
    const bool aval = (gar < M);
    const float* Ap = A + (size_t)gar * K + aseg * 16;
    char* sArow = smem + arow * PITCHB + aseg * 64;

    // B loader: col bn = tid, 32 strided k
    const int bn = tid;
    const float* Bp = B + col0 + bn;
    char* sBrow = smem + ATILE + bn * PITCHB;

    float dacc[32][4];
    #pragma unroll
    for (int t = 0; t < 32; t++)
        #pragma unroll
        for (int c = 0; c < 4; c++) dacc[t][c] = 0.f;

    const int NBLK = K >> 5;

    // ---- pack one k-block into buffer offset bufo ----
    auto store_tiles = [&](int bufo, const float4 a4[4], const float bl[32]) {
        char* dst = sArow + bufo;
        #pragma unroll
        for (int q = 0; q < 4; q++) {
            const float v[4] = {a4[q].x, a4[q].y, a4[q].z, a4[q].w};
            #pragma unroll
            for (int pp = 0; pp < 2; pp++) {          // pair (k,k+1)
                const float v0 = v[pp*2], v1 = v[pp*2+1];
                const uint32_t h01 = cvt_f16x2(v1, v0);   // [f16(v0) | f16(v1)<<16]
                const uint32_t w0 = __byte_perm(h01, h01, 0x1010); // ah0|ah0
                const uint32_t w1 = __byte_perm(h01, h01, 0x3232); // ah1|ah1
                asm volatile("st.shared.v2.b32 [%0], {%1,%2};"
                             :: "r"(smem_u32(dst) + (q*2 + pp) * 8), "r"(w0), "r"(w1));
            }
        }
        char* dstb = sBrow + bufo;
        #pragma unroll
        for (int j = 0; j < 8; j++) {                 // pair (k,k+1)
            const float v0 = bl[2*j], v1 = bl[2*j+1];
            const uint32_t bh01 = cvt_f16x2(v1, v0);
            const __half2 hp = *reinterpret_cast<const __half2*>(&bh01);
            const float2 f = __half22float2(hp);      // f.x=f16(v0), f.y=f16(v1)
            const uint32_t bl01 = cvt_f16x2(v1 - f.y, v0 - f.x);
            const uint32_t w0 = __byte_perm(bh01, bl01, 0x5410); // bh0|bl0
            const uint32_t w1 = __byte_perm(bh01, bl01, 0x7632); // bh1|bl1
            asm volatile("st.shared.v2.b32 [%0], {%1,%2};"
                         :: "r"(smem_u32(dstb) + j * 8), "r"(w0), "r"(w1));
        }
        #pragma unroll
        for (int j = 8; j < 16; j++) {
            const float v0 = bl[2*j], v1 = bl[2*j+1];
            const uint32_t bh01 = cvt_f16x2(v1, v0);
            const __half2 hp = *reinterpret_cast<const __half2*>(&bh01);
            const float2 f = __half22float2(hp);
            const uint32_t bl01 = cvt_f16x2(v1 - f.y, v0 - f.x);
            const uint32_t w0 = __byte_perm(bh01, bl01, 0x5410);
            const uint32_t w1 = __byte_perm(bh01, bl01, 0x7632);
            asm volatile("st.shared.v2.b32 [%0], {%1,%2};"
                         :: "r"(smem_u32(dstb) + j * 8), "r"(w0), "r"(w1));
        }
    };

    // ---- preload block 0 ----
    {
        float4 a4[4]; float bl[32];
        #pragma unroll
        for (int q = 0; q < 4; q++)
            a4[q] = aval ? *reinterpret_cast<const float4*>(Ap + q * 4)
                         : make_float4(0.f, 0.f, 0.f, 0.f);
        #pragma unroll
        for (int i = 0; i < 32; i++) bl[i] = Bp[(size_t)i * N];
        store_tiles(0, a4, bl);
    }
    __syncthreads();

    int buf = 0;
    for (int blk = 0; blk < NBLK; blk++) {
        float4 a4[4]; float bl[32];
        const bool more = (blk + 1 < NBLK);
        if (more) {
            const float* Apn = Ap + (blk + 1) * 32;
            const float* Bpn = Bp + (size_t)(blk + 1) * 32 * N;
            #pragma unroll
            for (int q = 0; q < 4; q++)
                a4[q] = aval ? *reinterpret_cast<const float4*>(Apn + q * 4)
                             : make_float4(0.f, 0.f, 0.f, 0.f);
            #pragma unroll
            for (int i = 0; i < 32; i++) bl[i] = Bpn[(size_t)i * N];
        }

        // ---- compute on buffer `buf`: 4 chunks of 16 slots ----
        const uint32_t sA  = sb + buf * BUFB;
        const uint32_t sBB = sA + ATILE;
        const uint32_t aAddrBase = sA + (uint32_t)(m0w + (lane & 15)) * PITCHB
                                      + ((lane >> 4) * 8) * 2;
        const int g = lane >> 3;
        const uint32_t bAddrBase = sBB + (uint32_t)(n0w + ((g >> 1) * 8) + (lane & 7)) * PITCHB
                                       + ((g & 1) * 8) * 2;
        #pragma unroll
        for (int kc = 0; kc < 4; kc++) {
            uint32_t af[4][4], bfr[8][2];
            #pragma unroll
            for (int mi = 0; mi < 4; mi++)
                LDSM4(af[mi][0], af[mi][1], af[mi][2], af[mi][3],
                      aAddrBase + (uint32_t)mi * 16 * PITCHB + kc * 32);
            #pragma unroll
            for (int p = 0; p < 4; p++)
                LDSM4(bfr[2*p][0], bfr[2*p][1], bfr[2*p+1][0], bfr[2*p+1][1],
                      bAddrBase + (uint32_t)p * 16 * PITCHB + kc * 32);
            #pragma unroll
            for (int mi = 0; mi < 4; mi++)
                #pragma unroll
                for (int nt = 0; nt < 8; nt++)
                    MMA_F16(dacc[mi * 8 + nt], af[mi], bfr[nt]);
        }

        if (more) {
            store_tiles((buf ^ 1) * BUFB, a4, bl);
            __syncthreads();
            buf ^= 1;
        }
    }

    // ---- epilogue ----
    #pragma unroll
    for (int mi = 0; mi < 4; mi++) {
        const int r0 = m0 + m0w + mi * 16 + (lane >> 2);
        #pragma unroll
        for (int nt = 0; nt < 8; nt++) {
            const int c = col0 + n0w + nt * 8 + (lane & 3) * 2;
            const float* d = dacc[mi * 8 + nt];
            float b0 = 0.f, b1 = 0.f;
            if (BIAS) { b0 = bias[c]; b1 = bias[c + 1]; }
            #pragma unroll
            for (int half = 0; half < 2; half++) {
                const int r = r0 + half * 8;
                if (r >= M) continue;
                float v0 = d[half * 2 + 0] + b0;
                float v1 = d[half * 2 + 1] + b1;
                if (GELU) {
                    v0 = 0.5f * v0 * (1.0f + erff(v0 * 0.70710678118654752f));
                    v1 = 0.5f * v1 * (1.0f + erff(v1 * 0.70710678118654752f));
                }
                if (RES) {
                    const float2 rv = *reinterpret_cast<const float2*>(
                        res + (size_t)r * N + c);
                    v0 += rv.x; v1 += rv.y;
                }
                *reinterpret_cast<float2*>(C + (size_t)r * N + c) =
                    make_float2(v0, v1);
            }
        }
    }
}

// ---------------- LayerNorm (R12) ----------------
__global__ __launch_bounds__(256) void ln_kernel(
    const float* __restrict__ x, const float* __restrict__ g,
    const float* __restrict__ b, float* __restrict__ out)
{
    const size_t t = blockIdx.x;
    const float* xr = x + t * DIM;
    const int tid = threadIdx.x;

    float v0 = xr[tid], v1 = xr[tid + 256], v2 = xr[tid + 512];
    float s  = v0 + v1 + v2;
    float ss = v0*v0 + v1*v1 + v2*v2;

    __shared__ float red[16];
    __shared__ float stat[2];
    #pragma unroll
    for (int o = 16; o; o >>= 1) {
        s  += __shfl_xor_sync(0xffffffffu, s,  o);
        ss += __shfl_xor_sync(0xffffffffu, ss, o);
    }
    if ((tid & 31) == 0) { red[tid >> 5] = s; red[(tid >> 5) + 8] = ss; }
    __syncthreads();
    if (tid == 0) {
        float a = 0.f, c = 0.f;
        #pragma unroll
        for (int i = 0; i < 8; i++) { a += red[i]; c += red[i + 8]; }
        float mu = a * (1.0f / DIM);
        float var = c * (1.0f / DIM) - mu * mu;
        stat[0] = mu;
        stat[1] = rsqrtf(var + 1e-5f);
    }
    __syncthreads();
    const float mu = stat[0], inv = stat[1];
    float* orow = out + t * DIM;
    orow[tid      ] = (v0 - mu) * inv * g[tid      ] + b[tid      ];
    orow[tid + 256] = (v1 - mu) * inv * g[tid + 256] + b[tid + 256];
    orow[tid + 512] = (v2 - mu) * inv * g[tid + 512] + b[tid + 512];
}

// ============ tensor-core flash attention (R15 winner, verbatim) ============
#define FPITCH   144
#define FPL      (64 * FPITCH)
#define FQH 0
#define FQL (FPL)
#define FKH (2*FPL)
#define FKL (3*FPL)
#define FVH (4*FPL)
#define FVL (5*FPL)
#define FSMAX (6*FPL)
#define FSSUM (FSMAX + 512)
#define FLSUM (FSSUM + 512)
#define FA2_SMEM (FLSUM + 256)

__global__ __launch_bounds__(256, 2) void fattn2_kernel(
    const float* __restrict__ qkv, float* __restrict__ O)
{
    extern __shared__ char sm[];
    const uint32_t sb = smem_u32(sm);
    const int tid = threadIdx.x;
    const int lane = tid & 31;
    const int wid = tid >> 5;
    const int wr = wid & 3, wc = wid >> 2;
    const int q4 = lane & 3, r4 = lane >> 2;

    const int bh = blockIdx.y;
    const int b = bh / HEADS, h = bh % HEADS;
    const int n0 = blockIdx.x * 64;
    const float* qb = qkv + (size_t)b * SEQ * QKVD + h * HD;
    const float* kb = qb + DIM;
    const float* vb = qb + 2 * DIM;

    const int lr = tid >> 2;
    const int lc = (tid & 3) * 16;

    auto cvst = [&](uint32_t ph, uint32_t pl, float4 v, int row, int ce) {
        const uint32_t h0 = cvt_bf16x2(v.y, v.x);
        const uint32_t l0 = cvt_bf16x2(v.y - __uint_as_float(h0 & 0xFFFF0000u),
                                       v.x - __uint_as_float(h0 << 16));
        const uint32_t h1 = cvt_bf16x2(v.w, v.z);
        const uint32_t l1 = cvt_bf16x2(v.w - __uint_as_float(h1 & 0xFFFF0000u),
                                       v.z - __uint_as_float(h1 << 16));
        const uint32_t off = row * FPITCH + ce * 2;
        asm volatile("st.shared.v2.b32 [%0], {%1,%2};" :: "r"(sb + ph + off), "r"(h0), "r"(h1));
        asm volatile("st.shared.v2.b32 [%0], {%1,%2};" :: "r"(sb + pl + off), "r"(l0), "r"(l1));
    };

    {
        const int n = n0 + lr;
        const float4* src = (n < SEQ)
            ? reinterpret_cast<const float4*>(qb + (size_t)n * QKVD + lc) : nullptr;
        #pragma unroll
        for (int c4 = 0; c4 < 4; c4++) {
            float4 v = src ? src[c4] : make_float4(0.f,0.f,0.f,0.f);
            v.x *= 0.125f; v.y *= 0.125f; v.z *= 0.125f; v.w *= 0.125f;
            cvst(FQH, FQL, v, lr, lc + c4 * 4);
        }
    }

    float o[8][4];
    float mA = -1e30f, mB = -1e30f, lA = 0.f, lB = 0.f;
    #pragma unroll
    for (int t = 0; t < 8; t++)
        #pragma unroll
        for (int c = 0; c < 4; c++) o[t][c] = 0.f;

    float* smax = reinterpret_cast<float*>(sm + FSMAX);
    float* ssum = reinterpret_cast<float*>(sm + FSSUM);
    const int sidx = (wc * 4 + wr) * 16;
    const int oidx = ((wc ^ 1) * 4 + wr) * 16;

    for (int k0 = 0; k0 < SEQ; k0 += 64) {
        __syncthreads();
        {
            const int m = k0 + lr;
            const float4* sk = (m < SEQ)
                ? reinterpret_cast<const float4*>(kb + (size_t)m * QKVD + lc) : nullptr;
            const float4* sv = (m < SEQ)
                ? reinterpret_cast<const float4*>(vb + (size_t)m * QKVD + lc) : nullptr;
            #pragma unroll
            for (int c4 = 0; c4 < 4; c4++) {
                float4 v = sk ? sk[c4] : make_float4(0.f,0.f,0.f,0.f);
                cvst(FKH, FKL, v, lr, lc + c4 * 4);
                float4 w = sv ? sv[c4] : make_float4(0.f,0.f,0.f,0.f);
                cvst(FVH, FVL, w, lr, lc + c4 * 4);
            }
        }
        __syncthreads();

        float s[4][4];
        #pragma unroll
        for (int t = 0; t < 4; t++)
            #pragma unroll
            for (int c = 0; c < 4; c++) s[t][c] = 0.f;

        const uint32_t qAddr = sb + (uint32_t)(16 * wr + (lane & 15)) * FPITCH
                                  + (lane >> 4) * 16;
        const int g = lane >> 3;
        const uint32_t kAddr = sb + FKH
            + (uint32_t)(wc * 32 + (g >> 1) * 8 + (lane & 7)) * FPITCH
            + (g & 1) * 16;

        #pragma unroll
        for (int ks = 0; ks < 4; ks++) {
            uint32_t qh[4], ql[4], kh[8], kl[8];
            LDSM4(qh[0], qh[1], qh[2], qh[3], qAddr + FQH + ks * 32);
            LDSM4(ql[0], ql[1], ql[2], ql[3], qAddr + FQL + ks * 32);
            #pragma unroll
            for (int t2 = 0; t2 < 2; t2++) {
                LDSM4(kh[t2*4], kh[t2*4+1], kh[t2*4+2], kh[t2*4+3],
                      kAddr + (uint32_t)t2 * 16 * FPITCH + ks * 32);
                LDSM4(kl[t2*4], kl[t2*4+1], kl[t2*4+2], kl[t2*4+3],
                      kAddr + (FKL - FKH) + (uint32_t)t2 * 16 * FPITCH + ks * 32);
            }
            #pragma unroll
            for (int t = 0; t < 4; t++) {
                MMA_BF16(s[t], qh, &kh[t*2]);
                MMA_BF16(s[t], qh, &kl[t*2]);
                MMA_BF16(s[t], ql, &kh[t*2]);
            }
        }

        #pragma unroll
        for (int t = 0; t < 4; t++) {
            const int key0 = k0 + wc * 32 + t * 8 + 2 * q4;
            if (key0 >= SEQ)     { s[t][0] = -1e30f; s[t][2] = -1e30f; }
            if (key0 + 1 >= SEQ) { s[t][1] = -1e30f; s[t][3] = -1e30f; }
        }

        float tmA = -1e30f, tmB = -1e30f;
        #pragma unroll
        for (int t = 0; t < 4; t++) {
            tmA = fmaxf(tmA, fmaxf(s[t][0], s[t][1]));
            tmB = fmaxf(tmB, fmaxf(s[t][2], s[t][3]));
        }
        tmA = fmaxf(tmA, __shfl_xor_sync(0xffffffffu, tmA, 1));
        tmA = fmaxf(tmA, __shfl_xor_sync(0xffffffffu, tmA, 2));
        tmB = fmaxf(tmB, __shfl_xor_sync(0xffffffffu, tmB, 1));
        tmB = fmaxf(tmB, __shfl_xor_sync(0xffffffffu, tmB, 2));
        if (q4 == 0) { smax[sidx + r4] = tmA; smax[sidx + r4 + 8] = tmB; }
        __syncthreads();
        tmA = fmaxf(tmA, smax[oidx + r4]);
        tmB = fmaxf(tmB, smax[oidx + r4 + 8]);

        const float nmA = fmaxf(mA, tmA), nmB = fmaxf(mB, tmB);
        const float fA = __expf(mA - nmA), fB = __expf(mB - nmB);
        mA = nmA; mB = nmB;

        float suA = 0.f, suB = 0.f;
        #pragma unroll
        for (int t = 0; t < 4; t++) {
            s[t][0] = __expf(s[t][0] - nmA); suA += s[t][0];
            s[t][1] = __expf(s[t][1] - nmA); suA += s[t][1];
            s[t][2] = __expf(s[t][2] - nmB); suB += s[t][2];
            s[t][3] = __expf(s[t][3] - nmB); suB += s[t][3];
        }
        suA += __shfl_xor_sync(0xffffffffu, suA, 1);
        suA += __shfl_xor_sync(0xffffffffu, suA, 2);
        suB += __shfl_xor_sync(0xffffffffu, suB, 1);
        suB += __shfl_xor_sync(0xffffffffu, suB, 2);
        if (q4 == 0) { ssum[sidx + r4] = suA; ssum[sidx + r4 + 8] = suB; }
        __syncthreads();
        lA = lA * fA + suA + ssum[oidx + r4];
        lB = lB * fB + suB + ssum[oidx + r4 + 8];

        #pragma unroll
        for (int t = 0; t < 8; t++) {
            o[t][0] *= fA; o[t][1] *= fA; o[t][2] *= fB; o[t][3] *= fB;
        }

        const uint32_t vAddr = sb + FVH
            + (uint32_t)(wc * 32 + (lane & 7) + ((lane >> 3) & 1) * 8) * FPITCH
            + (lane >> 4) * 16;
        #pragma unroll
        for (int ks = 0; ks < 2; ks++) {
            uint32_t ph[4], pl[4];
            #pragma unroll
            for (int half = 0; half < 2; half++) {
                const float* sj = s[2 * ks + half];
                const uint32_t hA = cvt_bf16x2(sj[1], sj[0]);
                const uint32_t lAw = cvt_bf16x2(
                    sj[1] - __uint_as_float(hA & 0xFFFF0000u),
                    sj[0] - __uint_as_float(hA << 16));
                const uint32_t hB = cvt_bf16x2(sj[3], sj[2]);
                const uint32_t lBw = cvt_bf16x2(
                    sj[3] - __uint_as_float(hB & 0xFFFF0000u),
                    sj[2] - __uint_as_float(hB << 16));
                ph[half * 2]     = hA;  ph[half * 2 + 1] = hB;
                pl[half * 2]     = lAw; pl[half * 2 + 1] = lBw;
            }
            #pragma unroll
            for (int dp = 0; dp < 4; dp++) {
                uint32_t vh[4], vl[4];
                LDSM4T(vh[0], vh[1], vh[2], vh[3],
                       vAddr + (uint32_t)(ks * 16) * FPITCH + dp * 32);
                LDSM4T(vl[0], vl[1], vl[2], vl[3],
                       vAddr + (FVL - FVH) + (uint32_t)(ks * 16) * FPITCH + dp * 32);
                const int dt = dp * 2;
                MMA_BF16(o[dt], ph, &vh[0]);
                MMA_BF16(o[dt], ph, &vl[0]);
                MMA_BF16(o[dt], pl, &vh[0]);
                MMA_BF16(o[dt + 1], ph, &vh[2]);
                MMA_BF16(o[dt + 1], ph, &vl[2]);
                MMA_BF16(o[dt + 1], pl, &vh[2]);
            }
        }
    }

    __syncthreads();

    float* lsum = reinterpret_cast<float*>(sm + FLSUM);
    if (wc == 0 && q4 == 0) {
        lsum[wr * 16 + r4] = lA;
        lsum[wr * 16 + r4 + 8] = lB;
    }
    float* obuf = reinterpret_cast<float*>(sm) + wc * 4096;
    {
        const int rA = wr * 16 + r4, rB = rA + 8;
        #pragma unroll
        for (int t = 0; t < 8; t++) {
            const int c = t * 8 + 2 * q4;
            obuf[rA * 64 + c]     = o[t][0];
            obuf[rA * 64 + c + 1] = o[t][1];
            obuf[rB * 64 + c]     = o[t][2];
            obuf[rB * 64 + c + 1] = o[t][3];
        }
    }
    __syncthreads();

    {
        const int n = n0 + lr;
        if (n < SEQ) {
            const float inv = 1.0f / lsum[lr];
            float* b0 = reinterpret_cast<float*>(sm) + lr * 64 + lc;
            float* b1 = b0 + 4096;
            float* dst = O + ((size_t)(b * SEQ + n)) * DIM + h * HD + lc;
            #pragma unroll
            for (int c4 = 0; c4 < 4; c4++) {
                float4 u = *reinterpret_cast<float4*>(b0 + c4 * 4);
                float4 v = *reinterpret_cast<float4*>(b1 + c4 * 4);
                float4 r = make_float4((u.x + v.x) * inv, (u.y + v.y) * inv,
                                       (u.z + v.z) * inv, (u.w + v.w) * inv);
                *reinterpret_cast<float4*>(dst + c4 * 4) = r;
            }
        }
    }
}

// ---------------- launch ----------------
extern "C" void kernel_launch(void* const* d_in, const int* in_sizes, int n_in,
                              void* d_out, int out_size)
{
    const float* x     = (const float*)d_in[0];
    const float* ln1_g = (const float*)d_in[1];
    const float* ln1_b = (const float*)d_in[2];
    const float* Wqkv  = (const float*)d_in[3];
    const float* Wproj = (const float*)d_in[4];
    const float* bproj = (const float*)d_in[5];
    const float* ln2_g = (const float*)d_in[6];
    const float* ln2_b = (const float*)d_in[7];
    const float* W1    = (const float*)d_in[8];
    const float* b1    = (const float*)d_in[9];
    const float* W2    = (const float*)d_in[10];
    const float* b2    = (const float*)d_in[11];
    float* out = (float*)d_out;

    void* p_arena;
    cudaGetSymbolAddress(&p_arena, g_arena);
    float* arena = (float*)p_arena;
    float* h_buf = arena;
    float* x2buf = arena + (size_t)NTOK * DIM;
    float* qkvb  = arena + (size_t)NTOK * DIM * 2;
    float* mbuf  = qkvb;

    cudaFuncSetAttribute(fattn2_kernel,
                         cudaFuncAttributeMaxDynamicSharedMemorySize, FA2_SMEM);
    cudaFuncSetAttribute(tcgemm_kernel<false,false,false>,
                         cudaFuncAttributeMaxDynamicSharedMemorySize, GEMM_SMEM);
    cudaFuncSetAttribute(tcgemm_kernel<true,false,true>,
                         cudaFuncAttributeMaxDynamicSharedMemorySize, GEMM_SMEM);
    cudaFuncSetAttribute(tcgemm_kernel<true,true,false>,
                         cudaFuncAttributeMaxDynamicSharedMemorySize, GEMM_SMEM);

    const int MT = (NTOK + 127) / 128;  // 289

    // 1. h = LN1(x)
    ln_kernel<<<NTOK, 256>>>(x, ln1_g, ln1_b, h_buf);
    // 2. qkv = h @ Wqkv
    tcgemm_kernel<false,false,false><<<dim3(QKVD/256, MT), 256, GEMM_SMEM>>>(
        h_buf, Wqkv, nullptr, nullptr, qkvb, NTOK, QKVD, DIM);
    // 3. tensor-core attention -> h_buf
    fattn2_kernel<<<dim3(10, BATCH*HEADS), 256, FA2_SMEM>>>(qkvb, h_buf);
    // 4. x2 = x + O @ Wproj + bproj
    tcgemm_kernel<true,false,true><<<dim3(DIM/256, MT), 256, GEMM_SMEM>>>(
        h_buf, Wproj, bproj, x, x2buf, NTOK, DIM, DIM);
    // 5. h = LN2(x2)
    ln_kernel<<<NTOK, 256>>>(x2buf, ln2_g, ln2_b, h_buf);
    // 6. m = gelu(h @ W1 + b1)
    tcgemm_kernel<true,true,false><<<dim3(HIDDEN/256, MT), 256, GEMM_SMEM>>>(
        h_buf, W1, b1, nullptr, mbuf, NTOK, HIDDEN, DIM);
    // 7. out = x2 + m @ W2 + b2
    tcgemm_kernel<true,false,true><<<dim3(DIM/256, MT), 256, GEMM_SMEM>>>(
        mbuf, W2, b2, x2buf, out, NTOK, DIM, HIDDEN);
}

// round 17
// speedup vs baseline: 1.8039x; 1.0398x over previous
#include <cuda_runtime.h>
#include <cuda_fp16.h>
#include <math.h>
#include <stdint.h>

#define DIM      768
#define HEADS    12
#define HD       64
#define HIDDEN   3072
#define SEQ      577
#define BATCH    64
#define NTOK     (BATCH*SEQ)  // 36928
#define QKVD     (3*DIM)      // 2304

// ---------------- scratch arena ----------------
#define ACT_FLOATS ((size_t)NTOK * DIM * 2 + (size_t)NTOK * HIDDEN)
#define WQKV_W  ((size_t)DIM * QKVD)
#define WPROJ_W ((size_t)DIM * DIM)
#define W1_W    ((size_t)DIM * HIDDEN)
#define W2_W    ((size_t)HIDDEN * DIM)
#define ARENA_WORDS (ACT_FLOATS + WQKV_W + WPROJ_W + W1_W + W2_W)
__device__ __align__(16) uint32_t g_arena[ARENA_WORDS];

// ---------------- helpers ----------------
__device__ __forceinline__ uint32_t smem_u32(const void* p) {
    uint32_t a;
    asm("{ .reg .u64 t; cvta.to.shared.u64 t, %1; cvt.u32.u64 %0, t; }"
        : "=r"(a) : "l"(p));
    return a;
}
__device__ __forceinline__ uint32_t cvt_bf16x2(float hi, float lo) {
    uint32_t r;
    asm("cvt.rn.bf16x2.f32 %0, %1, %2;" : "=r"(r) : "f"(hi), "f"(lo));
    return r;
}
__device__ __forceinline__ uint32_t cvt_f16x2(float hi, float lo) {
    uint32_t r;
    asm("cvt.rn.f16x2.f32 %0, %1, %2;" : "=r"(r) : "f"(hi), "f"(lo));
    return r;
}

#define LDSM4(r0, r1, r2, r3, addr) \
    asm volatile("ldmatrix.sync.aligned.m8n8.x4.shared.b16 {%0,%1,%2,%3}, [%4];" \
                 : "=r"(r0), "=r"(r1), "=r"(r2), "=r"(r3) : "r"(addr))
#define LDSM4T(r0, r1, r2, r3, addr) \
    asm volatile("ldmatrix.sync.aligned.m8n8.x4.trans.shared.b16 {%0,%1,%2,%3}, [%4];" \
                 : "=r"(r0), "=r"(r1), "=r"(r2), "=r"(r3) : "r"(addr))

#define MMA_BF16(d, a, b) \
    asm volatile("mma.sync.aligned.m16n8k16.row.col.f32.bf16.bf16.f32 " \
                 "{%0,%1,%2,%3}, {%4,%5,%6,%7}, {%8,%9}, {%0,%1,%2,%3};" \
                 : "+f"((d)[0]), "+f"((d)[1]), "+f"((d)[2]), "+f"((d)[3]) \
                 : "r"((a)[0]), "r"((a)[1]), "r"((a)[2]), "r"((a)[3]), \
                   "r"((b)[0]), "r"((b)[1]))
#define MMA_F16(d, a, b) \
    asm volatile("mma.sync.aligned.m16n8k16.row.col.f32.f16.f16.f32 " \
                 "{%0,%1,%2,%3}, {%4,%5,%6,%7}, {%8,%9}, {%0,%1,%2,%3};" \
                 : "+f"((d)[0]), "+f"((d)[1]), "+f"((d)[2]), "+f"((d)[3]) \
                 : "r"((a)[0]), "r"((a)[1]), "r"((a)[2]), "r"((a)[3]), \
                   "r"((b)[0]), "r"((b)[1]))

// ===== fp16 2-term split GEMM, pre-packed B words (bh|bl<<16, [K][N]) =====
// Slots per real k: A=[ah,ah], B=[bh,bl]. 4 k16 chunks per 32 real k.
#define PITCHB   144                    // 64 slots * 2B + 16 pad
#define ATILE    (128 * PITCHB)         // 18432
#define BTILE    (256 * PITCHB)         // 36864
#define BUFB     (ATILE + BTILE)        // 55296
#define GEMM_SMEM (2 * BUFB)            // 110592

template<bool BIAS, bool GELU, bool RES>
__global__ __launch_bounds__(256, 1) void tcgemm_kernel(
    const float* __restrict__ A, const uint32_t* __restrict__ Bx,
    const float* __restrict__ bias, const float* __restrict__ res,
    float* __restrict__ C, int M, int N, int K)
{
    extern __shared__ char smem[];
    const uint32_t sb = smem_u32(smem);
    const int tid  = threadIdx.x;
    const int lane = tid & 31;
    const int wid  = tid >> 5;
    const int wr = wid >> 2, wc = wid & 3;        // warp grid 2 x 4
    const int m0w = wr * 64, n0w = wc * 64;       // warp tile 64 x 64

    const int m0 = blockIdx.y * 128, col0 = blockIdx.x * 256;

    // A loader: row = tid/2, seg covers 16 floats -> 32 slots = 64 B
    const int arow = tid >> 1, aseg = tid & 1;
    const int gar = m0 + arow;
    const bool aval = (gar < M);
    const float* Ap = A + (size_t)gar * K + aseg * 16;
    char* sArow = smem + arow * PITCHB + aseg * 64;

    // B loader: col bn = tid, 32 strided packed words (coalesced across warp)
    const int bn = tid;
    const uint32_t* Bp = Bx + col0 + bn;
    char* sBrow = smem + ATILE + bn * PITCHB;

    float dacc[32][4];
    #pragma unroll
    for (int t = 0; t < 32; t++)
        #pragma unroll
        for (int c = 0; c < 4; c++) dacc[t][c] = 0.f;

    const int NBLK = K >> 5;

    // ---- pack one k-block into buffer offset bufo ----
    auto store_tiles = [&](int bufo, const float4 a4[4], const uint32_t wb[32]) {
        char* dst = sArow + bufo;
        #pragma unroll
        for (int q = 0; q < 4; q++) {
            const float v[4] = {a4[q].x, a4[q].y, a4[q].z, a4[q].w};
            #pragma unroll
            for (int pp = 0; pp < 2; pp++) {          // pair (k,k+1)
                const float v0 = v[pp*2], v1 = v[pp*2+1];
                const uint32_t h01 = cvt_f16x2(v1, v0);
                const uint32_t w0 = __byte_perm(h01, h01, 0x1010); // ah0|ah0
                const uint32_t w1 = __byte_perm(h01, h01, 0x3232); // ah1|ah1
                asm volatile("st.shared.v2.b32 [%0], {%1,%2};"
                             :: "r"(smem_u32(dst) + (q*2 + pp) * 8), "r"(w0), "r"(w1));
            }
        }
        char* dstb = sBrow + bufo;
        #pragma unroll
        for (int j = 0; j < 16; j++) {                // words already packed
            asm volatile("st.shared.v2.b32 [%0], {%1,%2};"
                         :: "r"(smem_u32(dstb) + j * 8),
                            "r"(wb[2*j]), "r"(wb[2*j+1]));
        }
    };

    // ---- preload block 0 ----
    {
        float4 a4[4]; uint32_t wb[32];
        #pragma unroll
        for (int q = 0; q < 4; q++)
            a4[q] = aval ? *reinterpret_cast<const float4*>(Ap + q * 4)
                         : make_float4(0.f, 0.f, 0.f, 0.f);
        #pragma unroll
        for (int i = 0; i < 32; i++) wb[i] = Bp[(size_t)i * N];
        store_tiles(0, a4, wb);
    }
    __syncthreads();

    int buf = 0;
    for (int blk = 0; blk < NBLK; blk++) {
        float4 a4[4]; uint32_t wb[32];
        const bool more = (blk + 1 < NBLK);
        if (more) {
            const float* Apn = Ap + (blk + 1) * 32;
            const uint32_t* Bpn = Bp + (size_t)(blk + 1) * 32 * N;
            #pragma unroll
            for (int q = 0; q < 4; q++)
                a4[q] = aval ? *reinterpret_cast<const float4*>(Apn + q * 4)
                             : make_float4(0.f, 0.f, 0.f, 0.f);
            #pragma unroll
            for (int i = 0; i < 32; i++) wb[i] = Bpn[(size_t)i * N];
        }

        // ---- compute on buffer `buf`: 4 chunks of 16 slots ----
        const uint32_t sA  = sb + buf * BUFB;
        const uint32_t sBB = sA + ATILE;
        const uint32_t aAddrBase = sA + (uint32_t)(m0w + (lane & 15)) * PITCHB
                                      + ((lane >> 4) * 8) * 2;
        const int g = lane >> 3;
        const uint32_t bAddrBase = sBB + (uint32_t)(n0w + ((g >> 1) * 8) + (lane & 7)) * PITCHB
                                       + ((g & 1) * 8) * 2;
        #pragma unroll
        for (int kc = 0; kc < 4; kc++) {
            uint32_t af[4][4], bfr[8][2];
            #pragma unroll
            for (int mi = 0; mi < 4; mi++)
                LDSM4(af[mi][0], af[mi][1], af[mi][2], af[mi][3],
                      aAddrBase + (uint32_t)mi * 16 * PITCHB + kc * 32);
            #pragma unroll
            for (int p = 0; p < 4; p++)
                LDSM4(bfr[2*p][0], bfr[2*p][1], bfr[2*p+1][0], bfr[2*p+1][1],
                      bAddrBase + (uint32_t)p * 16 * PITCHB + kc * 32);
            #pragma unroll
            for (int mi = 0; mi < 4; mi++)
                #pragma unroll
                for (int nt = 0; nt < 8; nt++)
                    MMA_F16(dacc[mi * 8 + nt], af[mi], bfr[nt]);
        }

        if (more) {
            store_tiles((buf ^ 1) * BUFB, a4, wb);
            __syncthreads();
            buf ^= 1;
        }
    }

    // ---- epilogue ----
    #pragma unroll
    for (int mi = 0; mi < 4; mi++) {
        const int r0 = m0 + m0w + mi * 16 + (lane >> 2);
        #pragma unroll
        for (int nt = 0; nt < 8; nt++) {
            const int c = col0 + n0w + nt * 8 + (lane & 3) * 2;
            const float* d = dacc[mi * 8 + nt];
            float b0 = 0.f, b1 = 0.f;
            if (BIAS) { b0 = bias[c]; b1 = bias[c + 1]; }
            #pragma unroll
            for (int half = 0; half < 2; half++) {
                const int r = r0 + half * 8;
                if (r >= M) continue;
                float v0 = d[half * 2 + 0] + b0;
                float v1 = d[half * 2 + 1] + b1;
                if (GELU) {
                    v0 = 0.5f * v0 * (1.0f + erff(v0 * 0.70710678118654752f));
                    v1 = 0.5f * v1 * (1.0f + erff(v1 * 0.70710678118654752f));
                }
                if (RES) {
                    const float2 rv = *reinterpret_cast<const float2*>(
                        res + (size_t)r * N + c);
                    v0 += rv.x; v1 += rv.y;
                }
                *reinterpret_cast<float2*>(C + (size_t)r * N + c) =
                    make_float2(v0, v1);
            }
        }
    }
}

// ---- weight pack: W [K][N] fp32 -> Wx [K][N] uint32 (f16 hi | f16 lo<<16) ----
__global__ __launch_bounds__(256) void splitw_kernel(
    const float* __restrict__ W, uint32_t* __restrict__ Wx, size_t total)
{
    const size_t idx = (size_t)blockIdx.x * 256 + threadIdx.x;
    if (idx >= total) return;
    const float v = W[idx];
    const __half bh = __float2half_rn(v);
    const __half bl = __float2half_rn(v - __half2float(bh));
    Wx[idx] = (uint32_t)__half_as_ushort(bh)
            | ((uint32_t)__half_as_ushort(bl) << 16);
}

// ---------------- LayerNorm (R12) ----------------
__global__ __launch_bounds__(256) void ln_kernel(
    const float* __restrict__ x, const float* __restrict__ g,
    const float* __restrict__ b, float* __restrict__ out)
{
    const size_t t = blockIdx.x;
    const float* xr = x + t * DIM;
    const int tid = threadIdx.x;

    float v0 = xr[tid], v1 = xr[tid + 256], v2 = xr[tid + 512];
    float s  = v0 + v1 + v2;
    float ss = v0*v0 + v1*v1 + v2*v2;

    __shared__ float red[16];
    __shared__ float stat[2];
    #pragma unroll
    for (int o = 16; o; o >>= 1) {
        s  += __shfl_xor_sync(0xffffffffu, s,  o);
        ss += __shfl_xor_sync(0xffffffffu, ss, o);
    }
    if ((tid & 31) == 0) { red[tid >> 5] = s; red[(tid >> 5) + 8] = ss; }
    __syncthreads();
    if (tid == 0) {
        float a = 0.f, c = 0.f;
        #pragma unroll
        for (int i = 0; i < 8; i++) { a += red[i]; c += red[i + 8]; }
        float mu = a * (1.0f / DIM);
        float var = c * (1.0f / DIM) - mu * mu;
        stat[0] = mu;
        stat[1] = rsqrtf(var + 1e-5f);
    }
    __syncthreads();
    const float mu = stat[0], inv = stat[1];
    float* orow = out + t * DIM;
    orow[tid      ] = (v0 - mu) * inv * g[tid      ] + b[tid      ];
    orow[tid + 256] = (v1 - mu) * inv * g[tid + 256] + b[tid + 256];
    orow[tid + 512] = (v2 - mu) * inv * g[tid + 512] + b[tid + 512];
}

// ============ tensor-core flash attention (R15 winner, verbatim) ============
#define FPITCH   144
#define FPL      (64 * FPITCH)
#define FQH 0
#define FQL (FPL)
#define FKH (2*FPL)
#define FKL (3*FPL)
#define FVH (4*FPL)
#define FVL (5*FPL)
#define FSMAX (6*FPL)
#define FSSUM (FSMAX + 512)
#define FLSUM (FSSUM + 512)
#define FA2_SMEM (FLSUM + 256)

__global__ __launch_bounds__(256, 2) void fattn2_kernel(
    const float* __restrict__ qkv, float* __restrict__ O)
{
    extern __shared__ char sm[];
    const uint32_t sb = smem_u32(sm);
    const int tid = threadIdx.x;
    const int lane = tid & 31;
    const int wid = tid >> 5;
    const int wr = wid & 3, wc = wid >> 2;
    const int q4 = lane & 3, r4 = lane >> 2;

    const int bh = blockIdx.y;
    const int b = bh / HEADS, h = bh % HEADS;
    const int n0 = blockIdx.x * 64;
    const float* qb = qkv + (size_t)b * SEQ * QKVD + h * HD;
    const float* kb = qb + DIM;
    const float* vb = qb + 2 * DIM;

    const int lr = tid >> 2;
    const int lc = (tid & 3) * 16;

    auto cvst = [&](uint32_t ph, uint32_t pl, float4 v, int row, int ce) {
        const uint32_t h0 = cvt_bf16x2(v.y, v.x);
        const uint32_t l0 = cvt_bf16x2(v.y - __uint_as_float(h0 & 0xFFFF0000u),
                                       v.x - __uint_as_float(h0 << 16));
        const uint32_t h1 = cvt_bf16x2(v.w, v.z);
        const uint32_t l1 = cvt_bf16x2(v.w - __uint_as_float(h1 & 0xFFFF0000u),
                                       v.z - __uint_as_float(h1 << 16));
        const uint32_t off = row * FPITCH + ce * 2;
        asm volatile("st.shared.v2.b32 [%0], {%1,%2};" :: "r"(sb + ph + off), "r"(h0), "r"(h1));
        asm volatile("st.shared.v2.b32 [%0], {%1,%2};" :: "r"(sb + pl + off), "r"(l0), "r"(l1));
    };

    {
        const int n = n0 + lr;
        const float4* src = (n < SEQ)
            ? reinterpret_cast<const float4*>(qb + (size_t)n * QKVD + lc) : nullptr;
        #pragma unroll
        for (int c4 = 0; c4 < 4; c4++) {
            float4 v = src ? src[c4] : make_float4(0.f,0.f,0.f,0.f);
            v.x *= 0.125f; v.y *= 0.125f; v.z *= 0.125f; v.w *= 0.125f;
            cvst(FQH, FQL, v, lr, lc + c4 * 4);
        }
    }

    float o[8][4];
    float mA = -1e30f, mB = -1e30f, lA = 0.f, lB = 0.f;
    #pragma unroll
    for (int t = 0; t < 8; t++)
        #pragma unroll
        for (int c = 0; c < 4; c++) o[t][c] = 0.f;

    float* smax = reinterpret_cast<float*>(sm + FSMAX);
    float* ssum = reinterpret_cast<float*>(sm + FSSUM);
    const int sidx = (wc * 4 + wr) * 16;
    const int oidx = ((wc ^ 1) * 4 + wr) * 16;

    for (int k0 = 0; k0 < SEQ; k0 += 64) {
        __syncthreads();
        {
            const int m = k0 + lr;
            const float4* sk = (m < SEQ)
                ? reinterpret_cast<const float4*>(kb + (size_t)m * QKVD + lc) : nullptr;
            const float4* sv = (m < SEQ)
                ? reinterpret_cast<const float4*>(vb + (size_t)m * QKVD + lc) : nullptr;
            #pragma unroll
            for (int c4 = 0; c4 < 4; c4++) {
                float4 v = sk ? sk[c4] : make_float4(0.f,0.f,0.f,0.f);
                cvst(FKH, FKL, v, lr, lc + c4 * 4);
                float4 w = sv ? sv[c4] : make_float4(0.f,0.f,0.f,0.f);
                cvst(FVH, FVL, w, lr, lc + c4 * 4);
            }
        }
        __syncthreads();

        float s[4][4];
        #pragma unroll
        for (int t = 0; t < 4; t++)
            #pragma unroll
            for (int c = 0; c < 4; c++) s[t][c] = 0.f;

        const uint32_t qAddr = sb + (uint32_t)(16 * wr + (lane & 15)) * FPITCH
                                  + (lane >> 4) * 16;
        const int g = lane >> 3;
        const uint32_t kAddr = sb + FKH
            + (uint32_t)(wc * 32 + (g >> 1) * 8 + (lane & 7)) * FPITCH
            + (g & 1) * 16;

        #pragma unroll
        for (int ks = 0; ks < 4; ks++) {
            uint32_t qh[4], ql[4], kh[8], kl[8];
            LDSM4(qh[0], qh[1], qh[2], qh[3], qAddr + FQH + ks * 32);
            LDSM4(ql[0], ql[1], ql[2], ql[3], qAddr + FQL + ks * 32);
            #pragma unroll
            for (int t2 = 0; t2 < 2; t2++) {
                LDSM4(kh[t2*4], kh[t2*4+1], kh[t2*4+2], kh[t2*4+3],
                      kAddr + (uint32_t)t2 * 16 * FPITCH + ks * 32);
                LDSM4(kl[t2*4], kl[t2*4+1], kl[t2*4+2], kl[t2*4+3],
                      kAddr + (FKL - FKH) + (uint32_t)t2 * 16 * FPITCH + ks * 32);
            }
            #pragma unroll
            for (int t = 0; t < 4; t++) {
                MMA_BF16(s[t], qh, &kh[t*2]);
                MMA_BF16(s[t], qh, &kl[t*2]);
                MMA_BF16(s[t], ql, &kh[t*2]);
            }
        }

        #pragma unroll
        for (int t = 0; t < 4; t++) {
            const int key0 = k0 + wc * 32 + t * 8 + 2 * q4;
            if (key0 >= SEQ)     { s[t][0] = -1e30f; s[t][2] = -1e30f; }
            if (key0 + 1 >= SEQ) { s[t][1] = -1e30f; s[t][3] = -1e30f; }
        }

        float tmA = -1e30f, tmB = -1e30f;
        #pragma unroll
        for (int t = 0; t < 4; t++) {
            tmA = fmaxf(tmA, fmaxf(s[t][0], s[t][1]));
            tmB = fmaxf(tmB, fmaxf(s[t][2], s[t][3]));
        }
        tmA = fmaxf(tmA, __shfl_xor_sync(0xffffffffu, tmA, 1));
        tmA = fmaxf(tmA, __shfl_xor_sync(0xffffffffu, tmA, 2));
        tmB = fmaxf(tmB, __shfl_xor_sync(0xffffffffu, tmB, 1));
        tmB = fmaxf(tmB, __shfl_xor_sync(0xffffffffu, tmB, 2));
        if (q4 == 0) { smax[sidx + r4] = tmA; smax[sidx + r4 + 8] = tmB; }
        __syncthreads();
        tmA = fmaxf(tmA, smax[oidx + r4]);
        tmB = fmaxf(tmB, smax[oidx + r4 + 8]);

        const float nmA = fmaxf(mA, tmA), nmB = fmaxf(mB, tmB);
        const float fA = __expf(mA - nmA), fB = __expf(mB - nmB);
        mA = nmA; mB = nmB;

        float suA = 0.f, suB = 0.f;
        #pragma unroll
        for (int t = 0; t < 4; t++) {
            s[t][0] = __expf(s[t][0] - nmA); suA += s[t][0];
            s[t][1] = __expf(s[t][1] - nmA); suA += s[t][1];
            s[t][2] = __expf(s[t][2] - nmB); suB += s[t][2];
            s[t][3] = __expf(s[t][3] - nmB); suB += s[t][3];
        }
        suA += __shfl_xor_sync(0xffffffffu, suA, 1);
        suA += __shfl_xor_sync(0xffffffffu, suA, 2);
        suB += __shfl_xor_sync(0xffffffffu, suB, 1);
        suB += __shfl_xor_sync(0xffffffffu, suB, 2);
        if (q4 == 0) { ssum[sidx + r4] = suA; ssum[sidx + r4 + 8] = suB; }
        __syncthreads();
        lA = lA * fA + suA + ssum[oidx + r4];
        lB = lB * fB + suB + ssum[oidx + r4 + 8];

        #pragma unroll
        for (int t = 0; t < 8; t++) {
            o[t][0] *= fA; o[t][1] *= fA; o[t][2] *= fB; o[t][3] *= fB;
        }

        const uint32_t vAddr = sb + FVH
            + (uint32_t)(wc * 32 + (lane & 7) + ((lane >> 3) & 1) * 8) * FPITCH
            + (lane >> 4) * 16;
        #pragma unroll
        for (int ks = 0; ks < 2; ks++) {
            uint32_t ph[4], pl[4];
            #pragma unroll
            for (int half = 0; half < 2; half++) {
                const float* sj = s[2 * ks + half];
                const uint32_t hA = cvt_bf16x2(sj[1], sj[0]);
                const uint32_t lAw = cvt_bf16x2(
                    sj[1] - __uint_as_float(hA & 0xFFFF0000u),
                    sj[0] - __uint_as_float(hA << 16));
                const uint32_t hB = cvt_bf16x2(sj[3], sj[2]);
                const uint32_t lBw = cvt_bf16x2(
                    sj[3] - __uint_as_float(hB & 0xFFFF0000u),
                    sj[2] - __uint_as_float(hB << 16));
                ph[half * 2]     = hA;  ph[half * 2 + 1] = hB;
                pl[half * 2]     = lAw; pl[half * 2 + 1] = lBw;
            }
            #pragma unroll
            for (int dp = 0; dp < 4; dp++) {
                uint32_t vh[4], vl[4];
                LDSM4T(vh[0], vh[1], vh[2], vh[3],
                       vAddr + (uint32_t)(ks * 16) * FPITCH + dp * 32);
                LDSM4T(vl[0], vl[1], vl[2], vl[3],
                       vAddr + (FVL - FVH) + (uint32_t)(ks * 16) * FPITCH + dp * 32);
                const int dt = dp * 2;
                MMA_BF16(o[dt], ph, &vh[0]);
                MMA_BF16(o[dt], ph, &vl[0]);
                MMA_BF16(o[dt], pl, &vh[0]);
                MMA_BF16(o[dt + 1], ph, &vh[2]);
                MMA_BF16(o[dt + 1], ph, &vl[2]);
                MMA_BF16(o[dt + 1], pl, &vh[2]);
            }
        }
    }

    __syncthreads();

    float* lsum = reinterpret_cast<float*>(sm + FLSUM);
    if (wc == 0 && q4 == 0) {
        lsum[wr * 16 + r4] = lA;
        lsum[wr * 16 + r4 + 8] = lB;
    }
    float* obuf = reinterpret_cast<float*>(sm) + wc * 4096;
    {
        const int rA = wr * 16 + r4, rB = rA + 8;
        #pragma unroll
        for (int t = 0; t < 8; t++) {
            const int c = t * 8 + 2 * q4;
            obuf[rA * 64 + c]     = o[t][0];
            obuf[rA * 64 + c + 1] = o[t][1];
            obuf[rB * 64 + c]     = o[t][2];
            obuf[rB * 64 + c + 1] = o[t][3];
        }
    }
    __syncthreads();

    {
        const int n = n0 + lr;
        if (n < SEQ) {
            const float inv = 1.0f / lsum[lr];
            float* b0 = reinterpret_cast<float*>(sm) + lr * 64 + lc;
            float* b1 = b0 + 4096;
            float* dst = O + ((size_t)(b * SEQ + n)) * DIM + h * HD + lc;
            #pragma unroll
            for (int c4 = 0; c4 < 4; c4++) {
                float4 u = *reinterpret_cast<float4*>(b0 + c4 * 4);
                float4 v = *reinterpret_cast<float4*>(b1 + c4 * 4);
                float4 r = make_float4((u.x + v.x) * inv, (u.y + v.y) * inv,
                                       (u.z + v.z) * inv, (u.w + v.w) * inv);
                *reinterpret_cast<float4*>(dst + c4 * 4) = r;
            }
        }
    }
}

// ---------------- launch ----------------
extern "C" void kernel_launch(void* const* d_in, const int* in_sizes, int n_in,
                              void* d_out, int out_size)
{
    const float* x     = (const float*)d_in[0];
    const float* ln1_g = (const float*)d_in[1];
    const float* ln1_b = (const float*)d_in[2];
    const float* Wqkv  = (const float*)d_in[3];
    const float* Wproj = (const float*)d_in[4];
    const float* bproj = (const float*)d_in[5];
    const float* ln2_g = (const float*)d_in[6];
    const float* ln2_b = (const float*)d_in[7];
    const float* W1    = (const float*)d_in[8];
    const float* b1    = (const float*)d_in[9];
    const float* W2    = (const float*)d_in[10];
    const float* b2    = (const float*)d_in[11];
    float* out = (float*)d_out;

    void* p_arena;
    cudaGetSymbolAddress(&p_arena, g_arena);
    uint32_t* aw = (uint32_t*)p_arena;
    float* h_buf = (float*)aw;
    float* x2buf = (float*)(aw + (size_t)NTOK * DIM);
    float* qkvb  = (float*)(aw + (size_t)NTOK * DIM * 2);
    float* mbuf  = qkvb;
    uint32_t* wqkvx  = aw + ACT_FLOATS;
    uint32_t* wprojx = wqkvx + WQKV_W;
    uint32_t* w1x    = wprojx + WPROJ_W;
    uint32_t* w2x    = w1x + W1_W;

    cudaFuncSetAttribute(fattn2_kernel,
                         cudaFuncAttributeMaxDynamicSharedMemorySize, FA2_SMEM);
    cudaFuncSetAttribute(tcgemm_kernel<false,false,false>,
                         cudaFuncAttributeMaxDynamicSharedMemorySize, GEMM_SMEM);
    cudaFuncSetAttribute(tcgemm_kernel<true,false,true>,
                         cudaFuncAttributeMaxDynamicSharedMemorySize, GEMM_SMEM);
    cudaFuncSetAttribute(tcgemm_kernel<true,true,false>,
                         cudaFuncAttributeMaxDynamicSharedMemorySize, GEMM_SMEM);

    const int MT = (NTOK + 127) / 128;  // 289

    // 0. pack weights (fp16 hi|lo words, same [K][N] layout), once per launch
    splitw_kernel<<<(int)((WQKV_W + 255)/256), 256>>>(Wqkv, wqkvx, WQKV_W);
    splitw_kernel<<<(int)((WPROJ_W + 255)/256), 256>>>(Wproj, wprojx, WPROJ_W);
    splitw_kernel<<<(int)((W1_W + 255)/256), 256>>>(W1, w1x, W1_W);
    splitw_kernel<<<(int)((W2_W + 255)/256), 256>>>(W2, w2x, W2_W);

    // 1. h = LN1(x)
    ln_kernel<<<NTOK, 256>>>(x, ln1_g, ln1_b, h_buf);
    // 2. qkv = h @ Wqkv
    tcgemm_kernel<false,false,false><<<dim3(QKVD/256, MT), 256, GEMM_SMEM>>>(
        h_buf, wqkvx, nullptr, nullptr, qkvb, NTOK, QKVD, DIM);
    // 3. tensor-core attention -> h_buf
    fattn2_kernel<<<dim3(10, BATCH*HEADS), 256, FA2_SMEM>>>(qkvb, h_buf);
    // 4. x2 = x + O @ Wproj + bproj
    tcgemm_kernel<true,false,true><<<dim3(DIM/256, MT), 256, GEMM_SMEM>>>(
        h_buf, wprojx, bproj, x, x2buf, NTOK, DIM, DIM);
    // 5. h = LN2(x2)
    ln_kernel<<<NTOK, 256>>>(x2buf, ln2_g, ln2_b, h_buf);
    // 6. m = gelu(h @ W1 + b1)
    tcgemm_kernel<true,true,false><<<dim3(HIDDEN/256, MT), 256, GEMM_SMEM>>>(
        h_buf, w1x, b1, nullptr, mbuf, NTOK, HIDDEN, DIM);
    // 7. out = x2 + m @ W2 + b2
    tcgemm_kernel<true,false,true><<<dim3(DIM/256, MT), 256, GEMM_SMEM>>>(
        mbuf, w2x, b2, x2buf, out, NTOK, DIM, HIDDEN);
}